// round 1
// baseline (speedup 1.0000x reference)
#include <cuda_runtime.h>
#include <math_constants.h>

// Problem shape (fixed by the dataset)
#define Bn 4
#define Hn 16
#define Sn 2048
#define Dn 64
#define BHn (Bn*Hn)

#define TQ 16          // query rows per CTA
#define TK 256         // key/value rows per smem tile
#define NKT (Sn/TK)    // 8 tiles
#define KROW 68        // floats per K/V smem row (64 + 4 pad -> conflict-free LDS.128)
#define NTHREADS 256

// dynamic smem: Q tile + K/V tile + full score tile
#define SMEM_FLOATS (TQ*Dn + TK*KROW + TQ*Sn)
#define SMEM_BYTES  (SMEM_FLOATS * 4)

typedef unsigned long long ull;

__device__ __forceinline__ ull fma2(ull a, ull b, ull c) {
    ull d;
    asm("fma.rn.f32x2 %0, %1, %2, %3;" : "=l"(d) : "l"(a), "l"(b), "l"(c));
    return d;
}
__device__ __forceinline__ float2 unpack2(ull v) {
    float2 f;
    asm("mov.b64 {%0, %1}, %2;" : "=f"(f.x), "=f"(f.y) : "l"(v));
    return f;
}
__device__ __forceinline__ ull bcast2(float x) {
    ull r;
    asm("mov.b64 %0, {%1, %1};" : "=l"(r) : "f"(x));
    return r;
}

__global__ __launch_bounds__(NTHREADS, 1)
void attn_kernel(const float* __restrict__ Q, const float* __restrict__ K,
                 const float* __restrict__ V, const int* __restrict__ mask,
                 float* __restrict__ Out, float* __restrict__ Attn)
{
    extern __shared__ float sm[];
    float* Qs  = sm;                 // TQ * 64
    float* KVs = Qs + TQ*Dn;         // TK * KROW
    float* Sc  = KVs + TK*KROW;      // TQ * Sn (full score/prob tile)

    const int t  = threadIdx.x;
    const int bh = blockIdx.y;
    const int b  = bh / Hn;
    const int q0 = blockIdx.x * TQ;
    const size_t qoff = ((size_t)bh*Sn + q0) * Dn;

    // ---- Load Q tile (TQ*Dn = 1024 floats, contiguous) ----
    {
        const float4* qg = (const float4*)(Q + qoff);
        ((float4*)Qs)[t] = qg[t];
    }

    // =======================  Phase 1: QK^T  =======================
    const int kg = t & 63;    // key group (thread's 4 keys: kg + 64*j)
    const int qg = t >> 6;    // query group (4 rows: qg*4 + i)

    for (int kt = 0; kt < NKT; ++kt) {
        const int kb = kt * TK;
        __syncthreads();
        // cooperative K tile load: 256 rows x 16 float4 (padded rows)
        {
            const float4* kgp = (const float4*)(K + ((size_t)bh*Sn + kb)*Dn);
            float4* kvs4 = (float4*)KVs;
            #pragma unroll
            for (int i = 0; i < 16; ++i) {
                int idx = t + i*NTHREADS;
                int row = idx >> 4, col = idx & 15;
                kvs4[row*(KROW/4) + col] = kgp[idx];
            }
        }
        __syncthreads();

        ull acc[4][4];
        #pragma unroll
        for (int i = 0; i < 4; ++i)
            #pragma unroll
            for (int j = 0; j < 4; ++j) acc[i][j] = 0ull;

        const ulonglong2* qsu = (const ulonglong2*)Qs;
        const ulonglong2* ksu = (const ulonglong2*)KVs;
        #pragma unroll
        for (int ds = 0; ds < 16; ++ds) {
            ulonglong2 qp[4], kp[4];
            #pragma unroll
            for (int i = 0; i < 4; ++i) qp[i] = qsu[(qg*4 + i)*16 + ds];
            #pragma unroll
            for (int j = 0; j < 4; ++j) kp[j] = ksu[(kg + 64*j)*(KROW/4) + ds];
            #pragma unroll
            for (int i = 0; i < 4; ++i)
                #pragma unroll
                for (int j = 0; j < 4; ++j) {
                    acc[i][j] = fma2(qp[i].x, kp[j].x, acc[i][j]);
                    acc[i][j] = fma2(qp[i].y, kp[j].y, acc[i][j]);
                }
        }

        // scores -> smem (scaled + masked)
        #pragma unroll
        for (int j = 0; j < 4; ++j) {
            const int kk = kb + kg + 64*j;
            const int mv = __ldg(mask + b*Sn + kk);
            #pragma unroll
            for (int i = 0; i < 4; ++i) {
                float2 f = unpack2(acc[i][j]);
                float s = (f.x + f.y) * 0.125f;
                if (mv == 0) s = -CUDART_INF_F;
                Sc[(qg*4 + i)*Sn + kk] = s;
            }
        }
    }
    __syncthreads();

    // =======================  Phase 2: softmax + attn write  =======================
    {
        const int w = t >> 5, lane = t & 31;
        #pragma unroll
        for (int rr = 0; rr < 2; ++rr) {
            const int r = w*2 + rr;
            float4* row4 = (float4*)(Sc + r*Sn);
            float m = -CUDART_INF_F;
            for (int k4 = lane; k4 < Sn/4; k4 += 32) {
                float4 v = row4[k4];
                m = fmaxf(m, fmaxf(fmaxf(v.x, v.y), fmaxf(v.z, v.w)));
            }
            #pragma unroll
            for (int o = 16; o > 0; o >>= 1) m = fmaxf(m, __shfl_xor_sync(0xffffffffu, m, o));

            float sum = 0.f;
            for (int k4 = lane; k4 < Sn/4; k4 += 32) {
                float4 v = row4[k4];
                v.x = __expf(v.x - m); v.y = __expf(v.y - m);
                v.z = __expf(v.z - m); v.w = __expf(v.w - m);
                row4[k4] = v;
                sum += (v.x + v.y) + (v.z + v.w);
            }
            #pragma unroll
            for (int o = 16; o > 0; o >>= 1) sum += __shfl_xor_sync(0xffffffffu, sum, o);
            const float inv = 1.0f / sum;

            float4* arow4 = (float4*)(Attn + ((size_t)bh*Sn + q0 + r)*Sn);
            for (int k4 = lane; k4 < Sn/4; k4 += 32) {
                float4 v = row4[k4];
                v.x *= inv; v.y *= inv; v.z *= inv; v.w *= inv;
                row4[k4]  = v;   // normalized probs kept for AV
                arow4[k4] = v;   // coalesced DRAM write (only attn round-trip)
            }
        }
    }

    // =======================  Phase 3: P @ V  =======================
    const int dg  = t & 15;         // 4-dim group (dims dg*4 .. dg*4+3)
    const int qg2 = (t >> 4) & 3;   // 4 query rows
    const int kc  = t >> 6;         // key chunk (4 chunks of 64 within tile)

    ull oacc[4][2];
    #pragma unroll
    for (int i = 0; i < 4; ++i) { oacc[i][0] = 0ull; oacc[i][1] = 0ull; }

    for (int kt = 0; kt < NKT; ++kt) {
        const int kb = kt * TK;
        __syncthreads();
        {
            const float4* vgp = (const float4*)(V + ((size_t)bh*Sn + kb)*Dn);
            float4* kvs4 = (float4*)KVs;
            #pragma unroll
            for (int i = 0; i < 16; ++i) {
                int idx = t + i*NTHREADS;
                int row = idx >> 4, col = idx & 15;
                kvs4[row*(KROW/4) + col] = vgp[idx];
            }
        }
        __syncthreads();

        const ulonglong2* vsu = (const ulonglong2*)KVs;
        #pragma unroll 4
        for (int kk = 0; kk < 64; ++kk) {
            const int k = kc*64 + kk;
            const ulonglong2 v2 = vsu[k*(KROW/4) + dg];
            const int kglob = kb + k;
            #pragma unroll
            for (int i = 0; i < 4; ++i) {
                const ull pp = bcast2(Sc[(qg2*4 + i)*Sn + kglob]);
                oacc[i][0] = fma2(pp, v2.x, oacc[i][0]);
                oacc[i][1] = fma2(pp, v2.y, oacc[i][1]);
            }
        }
    }
    __syncthreads();

    // reduce 4 key-chunk partials via smem (Sc is free now)
    #pragma unroll
    for (int i = 0; i < 4; ++i) {
        float2 a  = unpack2(oacc[i][0]);
        float2 b2 = unpack2(oacc[i][1]);
        const int base = kc*1024 + (qg2*4 + i)*64 + dg*4;
        Sc[base+0] = a.x;  Sc[base+1] = a.y;
        Sc[base+2] = b2.x; Sc[base+3] = b2.y;
    }
    __syncthreads();
    {
        const float4* p = (const float4*)Sc;
        float4 a = p[t], b4 = p[256+t], c = p[512+t], d4 = p[768+t];
        a.x += b4.x + c.x + d4.x;
        a.y += b4.y + c.y + d4.y;
        a.z += b4.z + c.z + d4.z;
        a.w += b4.w + c.w + d4.w;
        ((float4*)(Out + qoff))[t] = a;   // contiguous 1024-float tile
    }
}

extern "C" void kernel_launch(void* const* d_in, const int* in_sizes, int n_in,
                              void* d_out, int out_size)
{
    const float* Q    = (const float*)d_in[0];
    const float* K    = (const float*)d_in[1];
    const float* V    = (const float*)d_in[2];
    const int*   mask = (const int*)d_in[3];

    float* Out  = (float*)d_out;
    float* Attn = Out + (size_t)BHn * Sn * Dn;   // tuple layout: (output, attn)

    cudaFuncSetAttribute(attn_kernel, cudaFuncAttributeMaxDynamicSharedMemorySize, SMEM_BYTES);

    dim3 grid(Sn / TQ, BHn);
    attn_kernel<<<grid, NTHREADS, SMEM_BYTES>>>(Q, K, V, mask, Out, Attn);
}

// round 3
// speedup vs baseline: 2.9128x; 2.9128x over previous
#include <cuda_runtime.h>
#include <cuda_fp16.h>
#include <cstdint>

// ---------------- problem shape ----------------
#define Bn 4
#define Hn 16
#define Sn 2048
#define Dn 64
#define BHn (Bn*Hn)
#define MQ 128            // queries per CTA
#define TN 128            // keys per smem tile
#define NTILES (Sn/TN)    // 16
#define NT 256            // threads, 8 warps

// ---------------- smem layout (bytes) ----------------
#define SM_QH   0
#define SM_QL   16384
#define SM_KH   32768
#define SM_KL   49152
#define SM_VH   65536
#define SM_MASK 81920
#define SM_RS   90112
#define SM_INV  90624
#define SMEM_BYTES 91136

__device__ __forceinline__ uint32_t swz(uint32_t o) { return o ^ ((o >> 3) & 0x70); }

__device__ __forceinline__ uint32_t s2u(const void* p) {
    uint32_t a;
    asm("{ .reg .u64 t; cvta.to.shared.u64 t, %1; cvt.u32.u64 %0, t; }" : "=r"(a) : "l"(p));
    return a;
}
__device__ __forceinline__ uint32_t ph2(float a, float b) {
    __half2 h = __floats2half2_rn(a, b);
    return *reinterpret_cast<uint32_t*>(&h);
}
__device__ __forceinline__ float hres(float x) {
    return x - __half2float(__float2half_rn(x));
}
__device__ __forceinline__ void ldsm4(uint32_t* r, uint32_t a) {
    asm volatile("ldmatrix.sync.aligned.m8n8.x4.shared.b16 {%0,%1,%2,%3}, [%4];"
        : "=r"(r[0]), "=r"(r[1]), "=r"(r[2]), "=r"(r[3]) : "r"(a));
}
__device__ __forceinline__ void ldsm4t(uint32_t* r, uint32_t a) {
    asm volatile("ldmatrix.sync.aligned.m8n8.x4.trans.shared.b16 {%0,%1,%2,%3}, [%4];"
        : "=r"(r[0]), "=r"(r[1]), "=r"(r[2]), "=r"(r[3]) : "r"(a));
}
__device__ __forceinline__ void mma16816(float* d, const uint32_t* a, const uint32_t* b) {
    asm volatile("mma.sync.aligned.m16n8k16.row.col.f32.f16.f16.f32 "
        "{%0,%1,%2,%3},{%4,%5,%6,%7},{%8,%9},{%0,%1,%2,%3};"
        : "+f"(d[0]), "+f"(d[1]), "+f"(d[2]), "+f"(d[3])
        : "r"(a[0]), "r"(a[1]), "r"(a[2]), "r"(a[3]), "r"(b[0]), "r"(b[1]));
}

// 128x64 fp32 tile -> fp16 hi+lo smem (swizzled 128B rows)
__device__ __forceinline__ void load_tile_hl(const float* __restrict__ g, char* hi, char* lo, int tid) {
    #pragma unroll
    for (int it = 0; it < 4; ++it) {
        int chunk = tid + it * NT;
        int r = chunk >> 3, c8 = chunk & 7;
        const float4* p = (const float4*)(g + r * Dn + c8 * 8);
        float4 f0 = p[0], f1 = p[1];
        uint4 hv, lv;
        hv.x = ph2(f0.x, f0.y); hv.y = ph2(f0.z, f0.w);
        hv.z = ph2(f1.x, f1.y); hv.w = ph2(f1.z, f1.w);
        lv.x = ph2(hres(f0.x), hres(f0.y)); lv.y = ph2(hres(f0.z), hres(f0.w));
        lv.z = ph2(hres(f1.x), hres(f1.y)); lv.w = ph2(hres(f1.z), hres(f1.w));
        uint32_t off = swz((uint32_t)(r * 128 + c8 * 16));
        *(uint4*)(hi + off) = hv;
        *(uint4*)(lo + off) = lv;
    }
}
// hi-only variant (V)
__device__ __forceinline__ void load_tile_h(const float* __restrict__ g, char* hi, int tid) {
    #pragma unroll
    for (int it = 0; it < 4; ++it) {
        int chunk = tid + it * NT;
        int r = chunk >> 3, c8 = chunk & 7;
        const float4* p = (const float4*)(g + r * Dn + c8 * 8);
        float4 f0 = p[0], f1 = p[1];
        uint4 hv;
        hv.x = ph2(f0.x, f0.y); hv.y = ph2(f0.z, f0.w);
        hv.z = ph2(f1.x, f1.y); hv.w = ph2(f1.z, f1.w);
        *(uint4*)(hi + swz((uint32_t)(r * 128 + c8 * 16))) = hv;
    }
}

// QK for 64-key chunk at local key offset j0: c_[nt] = Q(16 rows of warp) x K(8 keys)
__device__ __forceinline__ void qk_chunk(uint32_t su, int w, int lane, int j0, float c_[8][4]) {
    #pragma unroll
    for (int nt = 0; nt < 8; ++nt)
        #pragma unroll
        for (int i = 0; i < 4; ++i) c_[nt][i] = 0.f;

    const int qr = w * 16 + (lane & 7) + ((lane >> 3) & 1) * 8;
    const uint32_t qcs = ((lane >> 4) & 1) * 16;
    const int krb = (lane & 7) + ((lane >> 4) & 1) * 8;
    const uint32_t kcs = ((lane >> 3) & 1) * 16;

    #pragma unroll
    for (int ks = 0; ks < 4; ++ks) {
        uint32_t qo = swz((uint32_t)(qr * 128 + ks * 32) + qcs);
        uint32_t ah[4], al[4];
        ldsm4(ah, su + SM_QH + qo);
        ldsm4(al, su + SM_QL + qo);
        #pragma unroll
        for (int pr = 0; pr < 4; ++pr) {
            int krow = j0 + pr * 16 + krb;
            uint32_t ko = swz((uint32_t)(krow * 128 + ks * 32) + kcs);
            uint32_t bh_[4], bl_[4];
            ldsm4(bh_, su + SM_KH + ko);
            ldsm4(bl_, su + SM_KL + ko);
            mma16816(c_[2 * pr],     ah, bh_);
            mma16816(c_[2 * pr],     ah, bl_);
            mma16816(c_[2 * pr],     al, bh_);
            mma16816(c_[2 * pr + 1], ah, bh_ + 2);
            mma16816(c_[2 * pr + 1], ah, bl_ + 2);
            mma16816(c_[2 * pr + 1], al, bh_ + 2);
        }
    }
}

__global__ __launch_bounds__(NT, 2)
void attn_hmma(const float* __restrict__ Q, const float* __restrict__ K,
               const float* __restrict__ V, const int* __restrict__ Mk,
               float* __restrict__ Out, float* __restrict__ Attn)
{
    extern __shared__ char smem[];
    const uint32_t su = s2u(smem);
    const int tid = threadIdx.x, w = tid >> 5, lane = tid & 31;
    const int bh = blockIdx.y, b = bh >> 4;
    const int q0 = blockIdx.x * MQ;
    const size_t qbase = ((size_t)bh * Sn + q0) * Dn;

    // mask -> smem
    int* ms = (int*)(smem + SM_MASK);
    #pragma unroll
    for (int i = 0; i < Sn / NT; ++i) ms[tid + i * NT] = Mk[(size_t)b * Sn + tid + i * NT];

    // Q tile -> smem hi/lo (persists across both passes)
    load_tile_hl(Q + qbase, smem + SM_QH, smem + SM_QL, tid);
    __syncthreads();

    // ============ Pass 1: row sums of exp(score) ============
    float rs0 = 0.f, rs1 = 0.f;
    for (int t = 0; t < NTILES; ++t) {
        if (t) __syncthreads();
        load_tile_hl(K + ((size_t)bh * Sn + t * TN) * Dn, smem + SM_KH, smem + SM_KL, tid);
        __syncthreads();
        #pragma unroll
        for (int c = 0; c < 2; ++c) {
            float c_[8][4];
            qk_chunk(su, w, lane, c * 64, c_);
            const int colb = t * TN + c * 64 + (lane & 3) * 2;
            #pragma unroll
            for (int nt = 0; nt < 8; ++nt) {
                int col = colb + nt * 8;
                int m0 = ms[col], m1 = ms[col + 1];
                rs0 += (m0 ? __expf(c_[nt][0] * 0.125f) : 0.f) + (m1 ? __expf(c_[nt][1] * 0.125f) : 0.f);
                rs1 += (m0 ? __expf(c_[nt][2] * 0.125f) : 0.f) + (m1 ? __expf(c_[nt][3] * 0.125f) : 0.f);
            }
        }
    }
    rs0 += __shfl_xor_sync(~0u, rs0, 1); rs0 += __shfl_xor_sync(~0u, rs0, 2);
    rs1 += __shfl_xor_sync(~0u, rs1, 1); rs1 += __shfl_xor_sync(~0u, rs1, 2);
    float* rsm = (float*)(smem + SM_RS);
    if ((lane & 3) == 0) {
        rsm[w * 16 + (lane >> 2)] = rs0;
        rsm[w * 16 + 8 + (lane >> 2)] = rs1;
    }
    __syncthreads();
    float* invm = (float*)(smem + SM_INV);
    if (tid < MQ) invm[tid] = 1.0f / rsm[tid];
    __syncthreads();
    const float inv0 = invm[w * 16 + (lane >> 2)];
    const float inv1 = invm[w * 16 + 8 + (lane >> 2)];

    // ============ Pass 2: attn write + PV ============
    float O[8][4];
    #pragma unroll
    for (int j = 0; j < 8; ++j)
        #pragma unroll
        for (int i = 0; i < 4; ++i) O[j][i] = 0.f;

    float* arow0 = Attn + ((size_t)bh * Sn + q0 + w * 16 + (lane >> 2)) * Sn;
    float* arow1 = arow0 + (size_t)8 * Sn;
    const int vrb = (lane & 7) + ((lane >> 3) & 1) * 8;
    const uint32_t vcs = ((lane >> 4) & 1) * 16;

    for (int t = 0; t < NTILES; ++t) {
        __syncthreads();
        load_tile_hl(K + ((size_t)bh * Sn + t * TN) * Dn, smem + SM_KH, smem + SM_KL, tid);
        load_tile_h (V + ((size_t)bh * Sn + t * TN) * Dn, smem + SM_VH, tid);
        __syncthreads();
        #pragma unroll
        for (int c = 0; c < 2; ++c) {
            float c_[8][4];
            qk_chunk(su, w, lane, c * 64, c_);
            uint32_t PH[8][2], PL[8][2];
            const int colb = t * TN + c * 64 + (lane & 3) * 2;
            #pragma unroll
            for (int nt = 0; nt < 8; ++nt) {
                int col = colb + nt * 8;
                int m0 = ms[col], m1 = ms[col + 1];
                float p0 = m0 ? __expf(c_[nt][0] * 0.125f) * inv0 : 0.f;
                float p1 = m1 ? __expf(c_[nt][1] * 0.125f) * inv0 : 0.f;
                float p2 = m0 ? __expf(c_[nt][2] * 0.125f) * inv1 : 0.f;
                float p3 = m1 ? __expf(c_[nt][3] * 0.125f) * inv1 : 0.f;
                *(float2*)(arow0 + col) = make_float2(p0, p1);
                *(float2*)(arow1 + col) = make_float2(p2, p3);
                PH[nt][0] = ph2(p0, p1);          PH[nt][1] = ph2(p2, p3);
                PL[nt][0] = ph2(hres(p0), hres(p1)); PL[nt][1] = ph2(hres(p2), hres(p3));
            }
            // PV: O += P(hi+lo) x V(hi)
            #pragma unroll
            for (int kp = 0; kp < 4; ++kp) {
                uint32_t pah[4] = { PH[2*kp][0], PH[2*kp][1], PH[2*kp+1][0], PH[2*kp+1][1] };
                uint32_t pal[4] = { PL[2*kp][0], PL[2*kp][1], PL[2*kp+1][0], PL[2*kp+1][1] };
                int vrow = c * 64 + kp * 16 + vrb;
                #pragma unroll
                for (int dp = 0; dp < 4; ++dp) {
                    uint32_t vo = swz((uint32_t)(vrow * 128 + dp * 32) + vcs);
                    uint32_t vb[4];
                    ldsm4t(vb, su + SM_VH + vo);
                    mma16816(O[2 * dp],     pah, vb);
                    mma16816(O[2 * dp],     pal, vb);
                    mma16816(O[2 * dp + 1], pah, vb + 2);
                    mma16816(O[2 * dp + 1], pal, vb + 2);
                }
            }
        }
    }

    // ============ O writeback ============
    float* orow0 = Out + ((size_t)bh * Sn + q0 + w * 16 + (lane >> 2)) * Dn;
    float* orow1 = orow0 + 8 * Dn;
    #pragma unroll
    for (int dt = 0; dt < 8; ++dt) {
        int col = dt * 8 + (lane & 3) * 2;
        *(float2*)(orow0 + col) = make_float2(O[dt][0], O[dt][1]);
        *(float2*)(orow1 + col) = make_float2(O[dt][2], O[dt][3]);
    }
}

extern "C" void kernel_launch(void* const* d_in, const int* in_sizes, int n_in,
                              void* d_out, int out_size)
{
    const float* Q    = (const float*)d_in[0];
    const float* K    = (const float*)d_in[1];
    const float* V    = (const float*)d_in[2];
    const int*   mask = (const int*)d_in[3];

    float* Out  = (float*)d_out;
    float* Attn = Out + (size_t)BHn * Sn * Dn;

    cudaFuncSetAttribute(attn_hmma, cudaFuncAttributeMaxDynamicSharedMemorySize, SMEM_BYTES);

    dim3 grid(Sn / MQ, BHn);
    attn_hmma<<<grid, NT, SMEM_BYTES>>>(Q, K, V, mask, Out, Attn);
}

// round 5
// speedup vs baseline: 3.5777x; 1.2283x over previous
#include <cuda_runtime.h>
#include <cuda_fp16.h>
#include <cstdint>

// ---------------- problem shape ----------------
#define Bn 4
#define Hn 16
#define Sn 2048
#define Dn 64
#define BHn (Bn*Hn)
#define MQ 128            // queries per CTA
#define TN 128            // keys per smem tile
#define NTILES (Sn/TN)    // 16
#define NT 256            // threads, 8 warps

// ---------------- smem layout (bytes) ----------------
#define SM_QH   0
#define SM_QL   16384
#define SM_KH   32768
#define SM_KL   49152
#define SM_VH   65536
#define SM_BIAS 81920     // 2048 floats: 0 or -1e30
#define SM_RS   90112
#define SM_INV  90624
#define SMEM_BYTES 91136

__device__ __forceinline__ uint32_t swz(uint32_t o) { return o ^ ((o >> 3) & 0x70); }

__device__ __forceinline__ uint32_t s2u(const void* p) {
    uint32_t a;
    asm("{ .reg .u64 t; cvta.to.shared.u64 t, %1; cvt.u32.u64 %0, t; }" : "=r"(a) : "l"(p));
    return a;
}
__device__ __forceinline__ uint32_t ph2(float a, float b) {
    __half2 h = __floats2half2_rn(a, b);
    return *reinterpret_cast<uint32_t*>(&h);
}
__device__ __forceinline__ float hres(float x) {
    return x - __half2float(__float2half_rn(x));
}
__device__ __forceinline__ void ldsm4(uint32_t* r, uint32_t a) {
    asm volatile("ldmatrix.sync.aligned.m8n8.x4.shared.b16 {%0,%1,%2,%3}, [%4];"
        : "=r"(r[0]), "=r"(r[1]), "=r"(r[2]), "=r"(r[3]) : "r"(a));
}
__device__ __forceinline__ void ldsm4t(uint32_t* r, uint32_t a) {
    asm volatile("ldmatrix.sync.aligned.m8n8.x4.trans.shared.b16 {%0,%1,%2,%3}, [%4];"
        : "=r"(r[0]), "=r"(r[1]), "=r"(r[2]), "=r"(r[3]) : "r"(a));
}
__device__ __forceinline__ void mma16816(float* d, const uint32_t* a, const uint32_t* b) {
    asm volatile("mma.sync.aligned.m16n8k16.row.col.f32.f16.f16.f32 "
        "{%0,%1,%2,%3},{%4,%5,%6,%7},{%8,%9},{%0,%1,%2,%3};"
        : "+f"(d[0]), "+f"(d[1]), "+f"(d[2]), "+f"(d[3])
        : "r"(a[0]), "r"(a[1]), "r"(a[2]), "r"(a[3]), "r"(b[0]), "r"(b[1]));
}

// 128x64 fp32 tile -> fp16 hi+lo smem (swizzled 128B rows). NT=256 -> 4 iters.
__device__ __forceinline__ void load_tile_hl(const float* __restrict__ g, char* hi, char* lo, int tid) {
    #pragma unroll
    for (int it = 0; it < 4; ++it) {
        int chunk = tid + it * NT;
        int r = chunk >> 3, c8 = chunk & 7;
        const float4* p = (const float4*)(g + r * Dn + c8 * 8);
        float4 f0 = p[0], f1 = p[1];
        uint4 hv, lv;
        hv.x = ph2(f0.x, f0.y); hv.y = ph2(f0.z, f0.w);
        hv.z = ph2(f1.x, f1.y); hv.w = ph2(f1.z, f1.w);
        lv.x = ph2(hres(f0.x), hres(f0.y)); lv.y = ph2(hres(f0.z), hres(f0.w));
        lv.z = ph2(hres(f1.x), hres(f1.y)); lv.w = ph2(hres(f1.z), hres(f1.w));
        uint32_t off = swz((uint32_t)(r * 128 + c8 * 16));
        *(uint4*)(hi + off) = hv;
        *(uint4*)(lo + off) = lv;
    }
}
// hi-only variant (V, and K in pass 1)
__device__ __forceinline__ void load_tile_h(const float* __restrict__ g, char* hi, int tid) {
    #pragma unroll
    for (int it = 0; it < 4; ++it) {
        int chunk = tid + it * NT;
        int r = chunk >> 3, c8 = chunk & 7;
        const float4* p = (const float4*)(g + r * Dn + c8 * 8);
        float4 f0 = p[0], f1 = p[1];
        uint4 hv;
        hv.x = ph2(f0.x, f0.y); hv.y = ph2(f0.z, f0.w);
        hv.z = ph2(f1.x, f1.y); hv.w = ph2(f1.z, f1.w);
        *(uint4*)(hi + swz((uint32_t)(r * 128 + c8 * 16))) = hv;
    }
}

// 3-term QK for 64-key chunk at local key offset j0 (pass 2; identical to round-3)
__device__ __forceinline__ void qk_chunk(uint32_t su, int w, int lane, int j0, float c_[8][4]) {
    #pragma unroll
    for (int nt = 0; nt < 8; ++nt)
        #pragma unroll
        for (int i = 0; i < 4; ++i) c_[nt][i] = 0.f;

    const int qr = w * 16 + (lane & 7) + ((lane >> 3) & 1) * 8;
    const uint32_t qcs = ((lane >> 4) & 1) * 16;
    const int krb = (lane & 7) + ((lane >> 4) & 1) * 8;
    const uint32_t kcs = ((lane >> 3) & 1) * 16;

    #pragma unroll
    for (int ks = 0; ks < 4; ++ks) {
        uint32_t qo = swz((uint32_t)(qr * 128 + ks * 32) + qcs);
        uint32_t ah[4], al[4];
        ldsm4(ah, su + SM_QH + qo);
        ldsm4(al, su + SM_QL + qo);
        #pragma unroll
        for (int pr = 0; pr < 4; ++pr) {
            int krow = j0 + pr * 16 + krb;
            uint32_t ko = swz((uint32_t)(krow * 128 + ks * 32) + kcs);
            uint32_t bh_[4], bl_[4];
            ldsm4(bh_, su + SM_KH + ko);
            ldsm4(bl_, su + SM_KL + ko);
            mma16816(c_[2 * pr],     ah, bh_);
            mma16816(c_[2 * pr],     ah, bl_);
            mma16816(c_[2 * pr],     al, bh_);
            mma16816(c_[2 * pr + 1], ah, bh_ + 2);
            mma16816(c_[2 * pr + 1], ah, bl_ + 2);
            mma16816(c_[2 * pr + 1], al, bh_ + 2);
        }
    }
}

__global__ __launch_bounds__(NT, 2)
void attn_hmma(const float* __restrict__ Q, const float* __restrict__ K,
               const float* __restrict__ V, const int* __restrict__ Mk,
               float* __restrict__ Out, float* __restrict__ Attn)
{
    extern __shared__ char smem[];
    const uint32_t su = s2u(smem);
    const int tid = threadIdx.x, w = tid >> 5, lane = tid & 31;
    const int bh = blockIdx.y, b = bh >> 4;
    const int q0 = blockIdx.x * MQ;
    const size_t qbase = ((size_t)bh * Sn + q0) * Dn;

    // mask -> float bias in smem (0 or -1e30); exp(s + bias) reproduces masking
    float* bias = (float*)(smem + SM_BIAS);
    #pragma unroll
    for (int i = 0; i < Sn / NT; ++i) {
        int idx = tid + i * NT;
        bias[idx] = Mk[(size_t)b * Sn + idx] ? 0.f : -1e30f;
    }

    // Q tile -> smem hi/lo (persists across both passes)
    load_tile_hl(Q + qbase, smem + SM_QH, smem + SM_QL, tid);
    __syncthreads();

    const int qr = w * 16 + (lane & 7) + ((lane >> 3) & 1) * 8;
    const uint32_t qcs = ((lane >> 4) & 1) * 16;
    const int krb = (lane & 7) + ((lane >> 4) & 1) * 8;
    const uint32_t kcs = ((lane >> 3) & 1) * 16;
    const int cb0 = (lane & 3) * 2;

    // ============ Pass 1: 1-term (hi x hi) row sums, Q frags hoisted ============
    uint32_t qf[4][4];
    #pragma unroll
    for (int ks = 0; ks < 4; ++ks)
        ldsm4(qf[ks], su + SM_QH + swz((uint32_t)(qr * 128 + ks * 32) + qcs));

    float rs0 = 0.f, rs1 = 0.f;
    for (int t = 0; t < NTILES; ++t) {
        if (t) __syncthreads();
        load_tile_h(K + ((size_t)bh * Sn + t * TN) * Dn, smem + SM_KH, tid);
        __syncthreads();
        #pragma unroll
        for (int c = 0; c < 2; ++c) {
            float c_[8][4];
            #pragma unroll
            for (int nt = 0; nt < 8; ++nt)
                #pragma unroll
                for (int i = 0; i < 4; ++i) c_[nt][i] = 0.f;
            #pragma unroll
            for (int ks = 0; ks < 4; ++ks) {
                #pragma unroll
                for (int pr = 0; pr < 4; ++pr) {
                    uint32_t bh_[4];
                    ldsm4(bh_, su + SM_KH + swz((uint32_t)((c * 64 + pr * 16 + krb) * 128 + ks * 32) + kcs));
                    mma16816(c_[2 * pr],     qf[ks], bh_);
                    mma16816(c_[2 * pr + 1], qf[ks], bh_ + 2);
                }
            }
            const float* bp = bias + t * TN + c * 64 + cb0;
            #pragma unroll
            for (int nt = 0; nt < 8; ++nt) {
                float2 bb = *(const float2*)(bp + nt * 8);
                rs0 += __expf(fmaf(c_[nt][0], 0.125f, bb.x)) + __expf(fmaf(c_[nt][1], 0.125f, bb.y));
                rs1 += __expf(fmaf(c_[nt][2], 0.125f, bb.x)) + __expf(fmaf(c_[nt][3], 0.125f, bb.y));
            }
        }
    }
    rs0 += __shfl_xor_sync(~0u, rs0, 1); rs0 += __shfl_xor_sync(~0u, rs0, 2);
    rs1 += __shfl_xor_sync(~0u, rs1, 1); rs1 += __shfl_xor_sync(~0u, rs1, 2);
    float* rsm = (float*)(smem + SM_RS);
    if ((lane & 3) == 0) {
        rsm[w * 16 + (lane >> 2)] = rs0;
        rsm[w * 16 + 8 + (lane >> 2)] = rs1;
    }
    __syncthreads();
    float* invm = (float*)(smem + SM_INV);
    if (tid < MQ) invm[tid] = 1.0f / rsm[tid];
    __syncthreads();
    const float inv0 = invm[w * 16 + (lane >> 2)];
    const float inv1 = invm[w * 16 + 8 + (lane >> 2)];

    // ============ Pass 2: 3-term QK, attn write, 2-term PV (round-3 verified) ============
    float O[8][4];
    #pragma unroll
    for (int j = 0; j < 8; ++j)
        #pragma unroll
        for (int i = 0; i < 4; ++i) O[j][i] = 0.f;

    float* arow0 = Attn + ((size_t)bh * Sn + q0 + w * 16 + (lane >> 2)) * Sn;
    float* arow1 = arow0 + (size_t)8 * Sn;
    const int vrb = (lane & 7) + ((lane >> 3) & 1) * 8;
    const uint32_t vcs = ((lane >> 4) & 1) * 16;

    for (int t = 0; t < NTILES; ++t) {
        __syncthreads();
        load_tile_hl(K + ((size_t)bh * Sn + t * TN) * Dn, smem + SM_KH, smem + SM_KL, tid);
        load_tile_h (V + ((size_t)bh * Sn + t * TN) * Dn, smem + SM_VH, tid);
        __syncthreads();
        #pragma unroll
        for (int c = 0; c < 2; ++c) {
            float c_[8][4];
            qk_chunk(su, w, lane, c * 64, c_);
            uint32_t PH[8][2], PL[8][2];
            const float* bp = bias + t * TN + c * 64 + cb0;
            #pragma unroll
            for (int nt = 0; nt < 8; ++nt) {
                int col = t * TN + c * 64 + nt * 8 + cb0;
                float2 bb = *(const float2*)(bp + nt * 8);
                float p0 = __expf(fmaf(c_[nt][0], 0.125f, bb.x)) * inv0;
                float p1 = __expf(fmaf(c_[nt][1], 0.125f, bb.y)) * inv0;
                float p2 = __expf(fmaf(c_[nt][2], 0.125f, bb.x)) * inv1;
                float p3 = __expf(fmaf(c_[nt][3], 0.125f, bb.y)) * inv1;
                *(float2*)(arow0 + col) = make_float2(p0, p1);
                *(float2*)(arow1 + col) = make_float2(p2, p3);
                PH[nt][0] = ph2(p0, p1);          PH[nt][1] = ph2(p2, p3);
                PL[nt][0] = ph2(hres(p0), hres(p1)); PL[nt][1] = ph2(hres(p2), hres(p3));
            }
            // PV: O += P(hi+lo) x V(hi)
            #pragma unroll
            for (int kp = 0; kp < 4; ++kp) {
                uint32_t pah[4] = { PH[2*kp][0], PH[2*kp][1], PH[2*kp+1][0], PH[2*kp+1][1] };
                uint32_t pal[4] = { PL[2*kp][0], PL[2*kp][1], PL[2*kp+1][0], PL[2*kp+1][1] };
                int vrow = c * 64 + kp * 16 + vrb;
                #pragma unroll
                for (int dp = 0; dp < 4; ++dp) {
                    uint32_t vo = swz((uint32_t)(vrow * 128 + dp * 32) + vcs);
                    uint32_t vb[4];
                    ldsm4t(vb, su + SM_VH + vo);
                    mma16816(O[2 * dp],     pah, vb);
                    mma16816(O[2 * dp],     pal, vb);
                    mma16816(O[2 * dp + 1], pah, vb + 2);
                    mma16816(O[2 * dp + 1], pal, vb + 2);
                }
            }
        }
    }

    // ============ O writeback ============
    float* orow0 = Out + ((size_t)bh * Sn + q0 + w * 16 + (lane >> 2)) * Dn;
    float* orow1 = orow0 + 8 * Dn;
    #pragma unroll
    for (int dt = 0; dt < 8; ++dt) {
        int col = dt * 8 + cb0;
        *(float2*)(orow0 + col) = make_float2(O[dt][0], O[dt][1]);
        *(float2*)(orow1 + col) = make_float2(O[dt][2], O[dt][3]);
    }
}

extern "C" void kernel_launch(void* const* d_in, const int* in_sizes, int n_in,
                              void* d_out, int out_size)
{
    const float* Q    = (const float*)d_in[0];
    const float* K    = (const float*)d_in[1];
    const float* V    = (const float*)d_in[2];
    const int*   mask = (const int*)d_in[3];

    float* Out  = (float*)d_out;
    float* Attn = Out + (size_t)BHn * Sn * Dn;

    cudaFuncSetAttribute(attn_hmma, cudaFuncAttributeMaxDynamicSharedMemorySize, SMEM_BYTES);

    dim3 grid(Sn / MQ, BHn);
    attn_hmma<<<grid, NT, SMEM_BYTES>>>(Q, K, V, mask, Out, Attn);
}

// round 6
// speedup vs baseline: 3.6241x; 1.0130x over previous
#include <cuda_runtime.h>
#include <cuda_fp16.h>
#include <cstdint>

// ---------------- problem shape ----------------
#define Bn 4
#define Hn 16
#define Sn 2048
#define Dn 64
#define BHn (Bn*Hn)
#define MQ 128            // queries per CTA
#define TN 128            // keys per smem tile
#define NTILES (Sn/TN)    // 16
#define NT 128            // threads, 4 warps; each warp owns 2 m-blocks (rows w*16 and w*16+64)

// ---------------- smem layout (bytes) ----------------
#define SM_QH   0
#define SM_QL   16384
#define SM_KH   32768
#define SM_KL   49152
#define SM_VH   65536
#define SM_BIAS 81920     // 2048 floats: 0 or -1e30
#define SM_RS   90112
#define SM_INV  90624
#define SMEM_BYTES 91136

__device__ __forceinline__ uint32_t swz(uint32_t o) { return o ^ ((o >> 3) & 0x70); }

__device__ __forceinline__ uint32_t s2u(const void* p) {
    uint32_t a;
    asm("{ .reg .u64 t; cvta.to.shared.u64 t, %1; cvt.u32.u64 %0, t; }" : "=r"(a) : "l"(p));
    return a;
}
__device__ __forceinline__ uint32_t ph2(float a, float b) {
    __half2 h = __floats2half2_rn(a, b);
    return *reinterpret_cast<uint32_t*>(&h);
}
__device__ __forceinline__ float hres(float x) {
    return x - __half2float(__float2half_rn(x));
}
__device__ __forceinline__ void ldsm4(uint32_t* r, uint32_t a) {
    asm volatile("ldmatrix.sync.aligned.m8n8.x4.shared.b16 {%0,%1,%2,%3}, [%4];"
        : "=r"(r[0]), "=r"(r[1]), "=r"(r[2]), "=r"(r[3]) : "r"(a));
}
__device__ __forceinline__ void ldsm4t(uint32_t* r, uint32_t a) {
    asm volatile("ldmatrix.sync.aligned.m8n8.x4.trans.shared.b16 {%0,%1,%2,%3}, [%4];"
        : "=r"(r[0]), "=r"(r[1]), "=r"(r[2]), "=r"(r[3]) : "r"(a));
}
__device__ __forceinline__ void mma16816(float* d, const uint32_t* a, const uint32_t* b) {
    asm volatile("mma.sync.aligned.m16n8k16.row.col.f32.f16.f16.f32 "
        "{%0,%1,%2,%3},{%4,%5,%6,%7},{%8,%9},{%0,%1,%2,%3};"
        : "+f"(d[0]), "+f"(d[1]), "+f"(d[2]), "+f"(d[3])
        : "r"(a[0]), "r"(a[1]), "r"(a[2]), "r"(a[3]), "r"(b[0]), "r"(b[1]));
}

// 128x64 fp32 tile -> fp16 hi+lo smem (swizzled 128B rows). NT=128 -> 8 iters.
__device__ __forceinline__ void load_tile_hl(const float* __restrict__ g, char* hi, char* lo, int tid) {
    #pragma unroll
    for (int it = 0; it < 8; ++it) {
        int chunk = tid + it * NT;
        int r = chunk >> 3, c8 = chunk & 7;
        const float4* p = (const float4*)(g + r * Dn + c8 * 8);
        float4 f0 = p[0], f1 = p[1];
        uint4 hv, lv;
        hv.x = ph2(f0.x, f0.y); hv.y = ph2(f0.z, f0.w);
        hv.z = ph2(f1.x, f1.y); hv.w = ph2(f1.z, f1.w);
        lv.x = ph2(hres(f0.x), hres(f0.y)); lv.y = ph2(hres(f0.z), hres(f0.w));
        lv.z = ph2(hres(f1.x), hres(f1.y)); lv.w = ph2(hres(f1.z), hres(f1.w));
        uint32_t off = swz((uint32_t)(r * 128 + c8 * 16));
        *(uint4*)(hi + off) = hv;
        *(uint4*)(lo + off) = lv;
    }
}
// hi-only variant (V, and K in pass 1)
__device__ __forceinline__ void load_tile_h(const float* __restrict__ g, char* hi, int tid) {
    #pragma unroll
    for (int it = 0; it < 8; ++it) {
        int chunk = tid + it * NT;
        int r = chunk >> 3, c8 = chunk & 7;
        const float4* p = (const float4*)(g + r * Dn + c8 * 8);
        float4 f0 = p[0], f1 = p[1];
        uint4 hv;
        hv.x = ph2(f0.x, f0.y); hv.y = ph2(f0.z, f0.w);
        hv.z = ph2(f1.x, f1.y); hv.w = ph2(f1.z, f1.w);
        *(uint4*)(hi + swz((uint32_t)(r * 128 + c8 * 16))) = hv;
    }
}

__global__ __launch_bounds__(NT, 2)
void attn_hmma(const float* __restrict__ Q, const float* __restrict__ K,
               const float* __restrict__ V, const int* __restrict__ Mk,
               float* __restrict__ Out, float* __restrict__ Attn)
{
    extern __shared__ char smem[];
    const uint32_t su = s2u(smem);
    const int tid = threadIdx.x, w = tid >> 5, lane = tid & 31;
    const int bh = blockIdx.y, b = bh >> 4;
    const int q0 = blockIdx.x * MQ;
    const size_t qbase = ((size_t)bh * Sn + q0) * Dn;

    // mask -> float bias in smem (0 or -1e30)
    float* bias = (float*)(smem + SM_BIAS);
    #pragma unroll
    for (int i = 0; i < Sn / NT; ++i) {
        int idx = tid + i * NT;
        bias[idx] = Mk[(size_t)b * Sn + idx] ? 0.f : -1e30f;
    }

    // Q tile -> smem hi/lo (persists across both passes)
    load_tile_hl(Q + qbase, smem + SM_QH, smem + SM_QL, tid);
    __syncthreads();

    // per-mb "virtual warp" row: mb=0 -> w, mb=1 -> w+4 (exactly round-5 warp w+4)
    const uint32_t qcs = ((lane >> 4) & 1) * 16;
    const int krb = (lane & 7) + ((lane >> 4) & 1) * 8;
    const uint32_t kcs = ((lane >> 3) & 1) * 16;
    const int cb0 = (lane & 3) * 2;
    int qr[2];
    qr[0] = w * 16 + (lane & 7) + ((lane >> 3) & 1) * 8;
    qr[1] = qr[0] + 64;

    // ============ Pass 1: 1-term (hi x hi), Q-hi frags hoisted, K shared over mb ============
    uint32_t qf[2][4][4];
    #pragma unroll
    for (int mb = 0; mb < 2; ++mb)
        #pragma unroll
        for (int ks = 0; ks < 4; ++ks)
            ldsm4(qf[mb][ks], su + SM_QH + swz((uint32_t)(qr[mb] * 128 + ks * 32) + qcs));

    float rs[2][2] = {{0.f, 0.f}, {0.f, 0.f}};
    for (int t = 0; t < NTILES; ++t) {
        if (t) __syncthreads();
        load_tile_h(K + ((size_t)bh * Sn + t * TN) * Dn, smem + SM_KH, tid);
        __syncthreads();
        #pragma unroll
        for (int c = 0; c < 2; ++c) {
            float c_[2][8][4];
            #pragma unroll
            for (int mb = 0; mb < 2; ++mb)
                #pragma unroll
                for (int nt = 0; nt < 8; ++nt)
                    #pragma unroll
                    for (int i = 0; i < 4; ++i) c_[mb][nt][i] = 0.f;
            #pragma unroll
            for (int ks = 0; ks < 4; ++ks) {
                #pragma unroll
                for (int pr = 0; pr < 4; ++pr) {
                    uint32_t bh_[4];
                    ldsm4(bh_, su + SM_KH + swz((uint32_t)((c * 64 + pr * 16 + krb) * 128 + ks * 32) + kcs));
                    #pragma unroll
                    for (int mb = 0; mb < 2; ++mb) {
                        mma16816(c_[mb][2 * pr],     qf[mb][ks], bh_);
                        mma16816(c_[mb][2 * pr + 1], qf[mb][ks], bh_ + 2);
                    }
                }
            }
            const float* bp = bias + t * TN + c * 64 + cb0;
            #pragma unroll
            for (int nt = 0; nt < 8; ++nt) {
                float2 bb = *(const float2*)(bp + nt * 8);
                #pragma unroll
                for (int mb = 0; mb < 2; ++mb) {
                    rs[mb][0] += __expf(fmaf(c_[mb][nt][0], 0.125f, bb.x)) + __expf(fmaf(c_[mb][nt][1], 0.125f, bb.y));
                    rs[mb][1] += __expf(fmaf(c_[mb][nt][2], 0.125f, bb.x)) + __expf(fmaf(c_[mb][nt][3], 0.125f, bb.y));
                }
            }
        }
    }
    #pragma unroll
    for (int mb = 0; mb < 2; ++mb)
        #pragma unroll
        for (int h = 0; h < 2; ++h) {
            rs[mb][h] += __shfl_xor_sync(~0u, rs[mb][h], 1);
            rs[mb][h] += __shfl_xor_sync(~0u, rs[mb][h], 2);
        }
    float* rsm = (float*)(smem + SM_RS);
    if ((lane & 3) == 0) {
        #pragma unroll
        for (int mb = 0; mb < 2; ++mb) {
            int r = (w + 4 * mb) * 16 + (lane >> 2);
            rsm[r]     = rs[mb][0];
            rsm[r + 8] = rs[mb][1];
        }
    }
    __syncthreads();
    float* invm = (float*)(smem + SM_INV);
    invm[tid] = 1.0f / rsm[tid];
    __syncthreads();
    float inv_[2][2];
    #pragma unroll
    for (int mb = 0; mb < 2; ++mb) {
        inv_[mb][0] = invm[(w + 4 * mb) * 16 + (lane >> 2)];
        inv_[mb][1] = invm[(w + 4 * mb) * 16 + 8 + (lane >> 2)];
    }

    // ============ Pass 2: 3-term QK, attn write, 2-term PV; K/V frags shared over mb ============
    float O[2][8][4];
    #pragma unroll
    for (int mb = 0; mb < 2; ++mb)
        #pragma unroll
        for (int j = 0; j < 8; ++j)
            #pragma unroll
            for (int i = 0; i < 4; ++i) O[mb][j][i] = 0.f;

    const int vrb = (lane & 7) + ((lane >> 3) & 1) * 8;
    const uint32_t vcs = ((lane >> 4) & 1) * 16;
    float* ar[2][2];
    #pragma unroll
    for (int mb = 0; mb < 2; ++mb) {
        ar[mb][0] = Attn + ((size_t)bh * Sn + q0 + (w + 4 * mb) * 16 + (lane >> 2)) * Sn;
        ar[mb][1] = ar[mb][0] + (size_t)8 * Sn;
    }

    for (int t = 0; t < NTILES; ++t) {
        __syncthreads();
        load_tile_hl(K + ((size_t)bh * Sn + t * TN) * Dn, smem + SM_KH, smem + SM_KL, tid);
        load_tile_h (V + ((size_t)bh * Sn + t * TN) * Dn, smem + SM_VH, tid);
        __syncthreads();
        #pragma unroll
        for (int c = 0; c < 2; ++c) {
            float c_[2][8][4];
            #pragma unroll
            for (int mb = 0; mb < 2; ++mb)
                #pragma unroll
                for (int nt = 0; nt < 8; ++nt)
                    #pragma unroll
                    for (int i = 0; i < 4; ++i) c_[mb][nt][i] = 0.f;
            #pragma unroll
            for (int ks = 0; ks < 4; ++ks) {
                uint32_t ah[2][4], al[2][4];
                #pragma unroll
                for (int mb = 0; mb < 2; ++mb) {
                    uint32_t qoff = swz((uint32_t)(qr[mb] * 128 + ks * 32) + qcs);
                    ldsm4(ah[mb], su + SM_QH + qoff);
                    ldsm4(al[mb], su + SM_QL + qoff);
                }
                #pragma unroll
                for (int pr = 0; pr < 4; ++pr) {
                    uint32_t koff = swz((uint32_t)((c * 64 + pr * 16 + krb) * 128 + ks * 32) + kcs);
                    uint32_t bh_[4], bl_[4];
                    ldsm4(bh_, su + SM_KH + koff);
                    ldsm4(bl_, su + SM_KL + koff);
                    #pragma unroll
                    for (int mb = 0; mb < 2; ++mb) {
                        mma16816(c_[mb][2 * pr],     ah[mb], bh_);
                        mma16816(c_[mb][2 * pr],     ah[mb], bl_);
                        mma16816(c_[mb][2 * pr],     al[mb], bh_);
                        mma16816(c_[mb][2 * pr + 1], ah[mb], bh_ + 2);
                        mma16816(c_[mb][2 * pr + 1], ah[mb], bl_ + 2);
                        mma16816(c_[mb][2 * pr + 1], al[mb], bh_ + 2);
                    }
                }
            }
            // epilogue: P = exp(s+bias)*inv, store attn, pack fragments
            uint32_t PH[2][8][2], PL[2][8][2];
            const float* bp = bias + t * TN + c * 64 + cb0;
            #pragma unroll
            for (int mb = 0; mb < 2; ++mb) {
                #pragma unroll
                for (int nt = 0; nt < 8; ++nt) {
                    int col = t * TN + c * 64 + nt * 8 + cb0;
                    float2 bb = *(const float2*)(bp + nt * 8);
                    float p0 = __expf(fmaf(c_[mb][nt][0], 0.125f, bb.x)) * inv_[mb][0];
                    float p1 = __expf(fmaf(c_[mb][nt][1], 0.125f, bb.y)) * inv_[mb][0];
                    float p2 = __expf(fmaf(c_[mb][nt][2], 0.125f, bb.x)) * inv_[mb][1];
                    float p3 = __expf(fmaf(c_[mb][nt][3], 0.125f, bb.y)) * inv_[mb][1];
                    *(float2*)(ar[mb][0] + col) = make_float2(p0, p1);
                    *(float2*)(ar[mb][1] + col) = make_float2(p2, p3);
                    PH[mb][nt][0] = ph2(p0, p1);          PH[mb][nt][1] = ph2(p2, p3);
                    PL[mb][nt][0] = ph2(hres(p0), hres(p1)); PL[mb][nt][1] = ph2(hres(p2), hres(p3));
                }
            }
            // PV: V fragments loaded once, consumed by both m-blocks
            #pragma unroll
            for (int kp = 0; kp < 4; ++kp) {
                uint32_t pah[2][4], pal[2][4];
                #pragma unroll
                for (int mb = 0; mb < 2; ++mb) {
                    pah[mb][0] = PH[mb][2*kp][0]; pah[mb][1] = PH[mb][2*kp][1];
                    pah[mb][2] = PH[mb][2*kp+1][0]; pah[mb][3] = PH[mb][2*kp+1][1];
                    pal[mb][0] = PL[mb][2*kp][0]; pal[mb][1] = PL[mb][2*kp][1];
                    pal[mb][2] = PL[mb][2*kp+1][0]; pal[mb][3] = PL[mb][2*kp+1][1];
                }
                int vrow = c * 64 + kp * 16 + vrb;
                #pragma unroll
                for (int dp = 0; dp < 4; ++dp) {
                    uint32_t vo = swz((uint32_t)(vrow * 128 + dp * 32) + vcs);
                    uint32_t vb[4];
                    ldsm4t(vb, su + SM_VH + vo);
                    #pragma unroll
                    for (int mb = 0; mb < 2; ++mb) {
                        mma16816(O[mb][2 * dp],     pah[mb], vb);
                        mma16816(O[mb][2 * dp],     pal[mb], vb);
                        mma16816(O[mb][2 * dp + 1], pah[mb], vb + 2);
                        mma16816(O[mb][2 * dp + 1], pal[mb], vb + 2);
                    }
                }
            }
        }
    }

    // ============ O writeback ============
    #pragma unroll
    for (int mb = 0; mb < 2; ++mb) {
        float* orow0 = Out + ((size_t)bh * Sn + q0 + (w + 4 * mb) * 16 + (lane >> 2)) * Dn;
        float* orow1 = orow0 + 8 * Dn;
        #pragma unroll
        for (int dt = 0; dt < 8; ++dt) {
            int col = dt * 8 + cb0;
            *(float2*)(orow0 + col) = make_float2(O[mb][dt][0], O[mb][dt][1]);
            *(float2*)(orow1 + col) = make_float2(O[mb][dt][2], O[mb][dt][3]);
        }
    }
}

extern "C" void kernel_launch(void* const* d_in, const int* in_sizes, int n_in,
                              void* d_out, int out_size)
{
    const float* Q    = (const float*)d_in[0];
    const float* K    = (const float*)d_in[1];
    const float* V    = (const float*)d_in[2];
    const int*   mask = (const int*)d_in[3];

    float* Out  = (float*)d_out;
    float* Attn = Out + (size_t)BHn * Sn * Dn;

    cudaFuncSetAttribute(attn_hmma, cudaFuncAttributeMaxDynamicSharedMemorySize, SMEM_BYTES);

    dim3 grid(Sn / MQ, BHn);
    attn_hmma<<<grid, NT, SMEM_BYTES>>>(Q, K, V, mask, Out, Attn);
}

// round 7
// speedup vs baseline: 3.6329x; 1.0024x over previous
#include <cuda_runtime.h>
#include <cuda_fp16.h>
#include <cstdint>

// ---------------- problem shape ----------------
#define Bn 4
#define Hn 16
#define Sn 2048
#define Dn 64
#define BHn (Bn*Hn)
#define MQ 128            // queries per CTA
#define TN 128            // keys per smem tile
#define NTILES (Sn/TN)    // 16
#define NT 128            // threads, 4 warps; each warp owns 2 m-blocks (rows w*16 and w*16+64)

// ---------------- smem layout (bytes) ----------------
#define SM_QH   0
#define SM_QL   16384
#define SM_KH   32768
#define SM_KL   49152
#define SM_VH   65536
#define SM_BIAS 81920     // 2048 floats: 0 or -1e30
#define SM_RS   90112
#define SM_INV  90624
#define SMEM_BYTES 91136

__device__ __forceinline__ uint32_t swz(uint32_t o) { return o ^ ((o >> 3) & 0x70); }

__device__ __forceinline__ uint32_t s2u(const void* p) {
    uint32_t a;
    asm("{ .reg .u64 t; cvta.to.shared.u64 t, %1; cvt.u32.u64 %0, t; }" : "=r"(a) : "l"(p));
    return a;
}
__device__ __forceinline__ uint32_t ph2(float a, float b) {
    __half2 h = __floats2half2_rn(a, b);
    return *reinterpret_cast<uint32_t*>(&h);
}
__device__ __forceinline__ float hres(float x) {
    return x - __half2float(__float2half_rn(x));
}
__device__ __forceinline__ void ldsm4(uint32_t* r, uint32_t a) {
    asm volatile("ldmatrix.sync.aligned.m8n8.x4.shared.b16 {%0,%1,%2,%3}, [%4];"
        : "=r"(r[0]), "=r"(r[1]), "=r"(r[2]), "=r"(r[3]) : "r"(a));
}
__device__ __forceinline__ void ldsm4t(uint32_t* r, uint32_t a) {
    asm volatile("ldmatrix.sync.aligned.m8n8.x4.trans.shared.b16 {%0,%1,%2,%3}, [%4];"
        : "=r"(r[0]), "=r"(r[1]), "=r"(r[2]), "=r"(r[3]) : "r"(a));
}
__device__ __forceinline__ void mma16816(float* d, const uint32_t* a, const uint32_t* b) {
    asm volatile("mma.sync.aligned.m16n8k16.row.col.f32.f16.f16.f32 "
        "{%0,%1,%2,%3},{%4,%5,%6,%7},{%8,%9},{%0,%1,%2,%3};"
        : "+f"(d[0]), "+f"(d[1]), "+f"(d[2]), "+f"(d[3])
        : "r"(a[0]), "r"(a[1]), "r"(a[2]), "r"(a[3]), "r"(b[0]), "r"(b[1]));
}

// 128x64 fp32 tile -> fp16 hi+lo smem (swizzled 128B rows). NT=128 -> 8 iters.
__device__ __forceinline__ void load_tile_hl(const float* __restrict__ g, char* hi, char* lo, int tid) {
    #pragma unroll
    for (int it = 0; it < 8; ++it) {
        int chunk = tid + it * NT;
        int r = chunk >> 3, c8 = chunk & 7;
        const float4* p = (const float4*)(g + r * Dn + c8 * 8);
        float4 f0 = p[0], f1 = p[1];
        uint4 hv, lv;
        hv.x = ph2(f0.x, f0.y); hv.y = ph2(f0.z, f0.w);
        hv.z = ph2(f1.x, f1.y); hv.w = ph2(f1.z, f1.w);
        lv.x = ph2(hres(f0.x), hres(f0.y)); lv.y = ph2(hres(f0.z), hres(f0.w));
        lv.z = ph2(hres(f1.x), hres(f1.y)); lv.w = ph2(hres(f1.z), hres(f1.w));
        uint32_t off = swz((uint32_t)(r * 128 + c8 * 16));
        *(uint4*)(hi + off) = hv;
        *(uint4*)(lo + off) = lv;
    }
}
// hi-only variant (V, and K in pass 1)
__device__ __forceinline__ void load_tile_h(const float* __restrict__ g, char* hi, int tid) {
    #pragma unroll
    for (int it = 0; it < 8; ++it) {
        int chunk = tid + it * NT;
        int r = chunk >> 3, c8 = chunk & 7;
        const float4* p = (const float4*)(g + r * Dn + c8 * 8);
        float4 f0 = p[0], f1 = p[1];
        uint4 hv;
        hv.x = ph2(f0.x, f0.y); hv.y = ph2(f0.z, f0.w);
        hv.z = ph2(f1.x, f1.y); hv.w = ph2(f1.z, f1.w);
        *(uint4*)(hi + swz((uint32_t)(r * 128 + c8 * 16))) = hv;
    }
}

__global__ __launch_bounds__(NT, 2)
void attn_hmma(const float* __restrict__ Q, const float* __restrict__ K,
               const float* __restrict__ V, const int* __restrict__ Mk,
               float* __restrict__ Out, float* __restrict__ Attn)
{
    extern __shared__ char smem[];
    const uint32_t su = s2u(smem);
    const int tid = threadIdx.x, w = tid >> 5, lane = tid & 31;
    const int bh = blockIdx.y, b = bh >> 4;
    const int q0 = blockIdx.x * MQ;
    const size_t qbase = ((size_t)bh * Sn + q0) * Dn;

    // mask -> float bias in smem (0 or -1e30)
    float* bias = (float*)(smem + SM_BIAS);
    #pragma unroll
    for (int i = 0; i < Sn / NT; ++i) {
        int idx = tid + i * NT;
        bias[idx] = Mk[(size_t)b * Sn + idx] ? 0.f : -1e30f;
    }

    // Q tile -> smem hi/lo (persists across both passes)
    load_tile_hl(Q + qbase, smem + SM_QH, smem + SM_QL, tid);
    __syncthreads();

    // per-mb "virtual warp" row: mb=0 -> w, mb=1 -> w+4 (exactly round-5 warp w+4)
    const uint32_t qcs = ((lane >> 4) & 1) * 16;
    const int krb = (lane & 7) + ((lane >> 4) & 1) * 8;
    const uint32_t kcs = ((lane >> 3) & 1) * 16;
    const int cb0 = (lane & 3) * 2;
    int qr[2];
    qr[0] = w * 16 + (lane & 7) + ((lane >> 3) & 1) * 8;
    qr[1] = qr[0] + 64;

    // ============ Pass 1: 1-term (hi x hi), Q-hi frags hoisted, K shared over mb ============
    uint32_t qf[2][4][4];
    #pragma unroll
    for (int mb = 0; mb < 2; ++mb)
        #pragma unroll
        for (int ks = 0; ks < 4; ++ks)
            ldsm4(qf[mb][ks], su + SM_QH + swz((uint32_t)(qr[mb] * 128 + ks * 32) + qcs));

    float rs[2][2] = {{0.f, 0.f}, {0.f, 0.f}};
    for (int t = 0; t < NTILES; ++t) {
        if (t) __syncthreads();
        load_tile_h(K + ((size_t)bh * Sn + t * TN) * Dn, smem + SM_KH, tid);
        __syncthreads();
        #pragma unroll
        for (int c = 0; c < 2; ++c) {
            float c_[2][8][4];
            #pragma unroll
            for (int mb = 0; mb < 2; ++mb)
                #pragma unroll
                for (int nt = 0; nt < 8; ++nt)
                    #pragma unroll
                    for (int i = 0; i < 4; ++i) c_[mb][nt][i] = 0.f;
            #pragma unroll
            for (int ks = 0; ks < 4; ++ks) {
                #pragma unroll
                for (int pr = 0; pr < 4; ++pr) {
                    uint32_t bh_[4];
                    ldsm4(bh_, su + SM_KH + swz((uint32_t)((c * 64 + pr * 16 + krb) * 128 + ks * 32) + kcs));
                    #pragma unroll
                    for (int mb = 0; mb < 2; ++mb) {
                        mma16816(c_[mb][2 * pr],     qf[mb][ks], bh_);
                        mma16816(c_[mb][2 * pr + 1], qf[mb][ks], bh_ + 2);
                    }
                }
            }
            const float* bp = bias + t * TN + c * 64 + cb0;
            #pragma unroll
            for (int nt = 0; nt < 8; ++nt) {
                float2 bb = *(const float2*)(bp + nt * 8);
                #pragma unroll
                for (int mb = 0; mb < 2; ++mb) {
                    rs[mb][0] += __expf(fmaf(c_[mb][nt][0], 0.125f, bb.x)) + __expf(fmaf(c_[mb][nt][1], 0.125f, bb.y));
                    rs[mb][1] += __expf(fmaf(c_[mb][nt][2], 0.125f, bb.x)) + __expf(fmaf(c_[mb][nt][3], 0.125f, bb.y));
                }
            }
        }
    }
    #pragma unroll
    for (int mb = 0; mb < 2; ++mb)
        #pragma unroll
        for (int h = 0; h < 2; ++h) {
            rs[mb][h] += __shfl_xor_sync(~0u, rs[mb][h], 1);
            rs[mb][h] += __shfl_xor_sync(~0u, rs[mb][h], 2);
        }
    float* rsm = (float*)(smem + SM_RS);
    if ((lane & 3) == 0) {
        #pragma unroll
        for (int mb = 0; mb < 2; ++mb) {
            int r = (w + 4 * mb) * 16 + (lane >> 2);
            rsm[r]     = rs[mb][0];
            rsm[r + 8] = rs[mb][1];
        }
    }
    __syncthreads();
    float* invm = (float*)(smem + SM_INV);
    invm[tid] = 1.0f / rsm[tid];
    __syncthreads();
    float inv_[2][2];
    #pragma unroll
    for (int mb = 0; mb < 2; ++mb) {
        inv_[mb][0] = invm[(w + 4 * mb) * 16 + (lane >> 2)];
        inv_[mb][1] = invm[(w + 4 * mb) * 16 + 8 + (lane >> 2)];
    }

    // ============ Pass 2: 3-term QK, attn write, 2-term PV; K/V frags shared over mb ============
    float O[2][8][4];
    #pragma unroll
    for (int mb = 0; mb < 2; ++mb)
        #pragma unroll
        for (int j = 0; j < 8; ++j)
            #pragma unroll
            for (int i = 0; i < 4; ++i) O[mb][j][i] = 0.f;

    const int vrb = (lane & 7) + ((lane >> 3) & 1) * 8;
    const uint32_t vcs = ((lane >> 4) & 1) * 16;
    float* ar[2][2];
    #pragma unroll
    for (int mb = 0; mb < 2; ++mb) {
        ar[mb][0] = Attn + ((size_t)bh * Sn + q0 + (w + 4 * mb) * 16 + (lane >> 2)) * Sn;
        ar[mb][1] = ar[mb][0] + (size_t)8 * Sn;
    }

    for (int t = 0; t < NTILES; ++t) {
        __syncthreads();
        load_tile_hl(K + ((size_t)bh * Sn + t * TN) * Dn, smem + SM_KH, smem + SM_KL, tid);
        load_tile_h (V + ((size_t)bh * Sn + t * TN) * Dn, smem + SM_VH, tid);
        __syncthreads();
        #pragma unroll
        for (int c = 0; c < 2; ++c) {
            float c_[2][8][4];
            #pragma unroll
            for (int mb = 0; mb < 2; ++mb)
                #pragma unroll
                for (int nt = 0; nt < 8; ++nt)
                    #pragma unroll
                    for (int i = 0; i < 4; ++i) c_[mb][nt][i] = 0.f;
            #pragma unroll
            for (int ks = 0; ks < 4; ++ks) {
                uint32_t ah[2][4], al[2][4];
                #pragma unroll
                for (int mb = 0; mb < 2; ++mb) {
                    uint32_t qoff = swz((uint32_t)(qr[mb] * 128 + ks * 32) + qcs);
                    ldsm4(ah[mb], su + SM_QH + qoff);
                    ldsm4(al[mb], su + SM_QL + qoff);
                }
                #pragma unroll
                for (int pr = 0; pr < 4; ++pr) {
                    uint32_t koff = swz((uint32_t)((c * 64 + pr * 16 + krb) * 128 + ks * 32) + kcs);
                    uint32_t bh_[4], bl_[4];
                    ldsm4(bh_, su + SM_KH + koff);
                    ldsm4(bl_, su + SM_KL + koff);
                    #pragma unroll
                    for (int mb = 0; mb < 2; ++mb) {
                        mma16816(c_[mb][2 * pr],     ah[mb], bh_);
                        mma16816(c_[mb][2 * pr],     ah[mb], bl_);
                        mma16816(c_[mb][2 * pr],     al[mb], bh_);
                        mma16816(c_[mb][2 * pr + 1], ah[mb], bh_ + 2);
                        mma16816(c_[mb][2 * pr + 1], ah[mb], bl_ + 2);
                        mma16816(c_[mb][2 * pr + 1], al[mb], bh_ + 2);
                    }
                }
            }
            // epilogue: P = exp(s+bias)*inv, store attn, pack fragments
            uint32_t PH[2][8][2], PL[2][8][2];
            const float* bp = bias + t * TN + c * 64 + cb0;
            #pragma unroll
            for (int mb = 0; mb < 2; ++mb) {
                #pragma unroll
                for (int nt = 0; nt < 8; ++nt) {
                    int col = t * TN + c * 64 + nt * 8 + cb0;
                    float2 bb = *(const float2*)(bp + nt * 8);
                    float p0 = __expf(fmaf(c_[mb][nt][0], 0.125f, bb.x)) * inv_[mb][0];
                    float p1 = __expf(fmaf(c_[mb][nt][1], 0.125f, bb.y)) * inv_[mb][0];
                    float p2 = __expf(fmaf(c_[mb][nt][2], 0.125f, bb.x)) * inv_[mb][1];
                    float p3 = __expf(fmaf(c_[mb][nt][3], 0.125f, bb.y)) * inv_[mb][1];
                    *(float2*)(ar[mb][0] + col) = make_float2(p0, p1);
                    *(float2*)(ar[mb][1] + col) = make_float2(p2, p3);
                    PH[mb][nt][0] = ph2(p0, p1);          PH[mb][nt][1] = ph2(p2, p3);
                    PL[mb][nt][0] = ph2(hres(p0), hres(p1)); PL[mb][nt][1] = ph2(hres(p2), hres(p3));
                }
            }
            // PV: V fragments loaded once, consumed by both m-blocks
            #pragma unroll
            for (int kp = 0; kp < 4; ++kp) {
                uint32_t pah[2][4], pal[2][4];
                #pragma unroll
                for (int mb = 0; mb < 2; ++mb) {
                    pah[mb][0] = PH[mb][2*kp][0]; pah[mb][1] = PH[mb][2*kp][1];
                    pah[mb][2] = PH[mb][2*kp+1][0]; pah[mb][3] = PH[mb][2*kp+1][1];
                    pal[mb][0] = PL[mb][2*kp][0]; pal[mb][1] = PL[mb][2*kp][1];
                    pal[mb][2] = PL[mb][2*kp+1][0]; pal[mb][3] = PL[mb][2*kp+1][1];
                }
                int vrow = c * 64 + kp * 16 + vrb;
                #pragma unroll
                for (int dp = 0; dp < 4; ++dp) {
                    uint32_t vo = swz((uint32_t)(vrow * 128 + dp * 32) + vcs);
                    uint32_t vb[4];
                    ldsm4t(vb, su + SM_VH + vo);
                    #pragma unroll
                    for (int mb = 0; mb < 2; ++mb) {
                        mma16816(O[mb][2 * dp],     pah[mb], vb);
                        mma16816(O[mb][2 * dp],     pal[mb], vb);
                        mma16816(O[mb][2 * dp + 1], pah[mb], vb + 2);
                        mma16816(O[mb][2 * dp + 1], pal[mb], vb + 2);
                    }
                }
            }
        }
    }

    // ============ O writeback ============
    #pragma unroll
    for (int mb = 0; mb < 2; ++mb) {
        float* orow0 = Out + ((size_t)bh * Sn + q0 + (w + 4 * mb) * 16 + (lane >> 2)) * Dn;
        float* orow1 = orow0 + 8 * Dn;
        #pragma unroll
        for (int dt = 0; dt < 8; ++dt) {
            int col = dt * 8 + cb0;
            *(float2*)(orow0 + col) = make_float2(O[mb][dt][0], O[mb][dt][1]);
            *(float2*)(orow1 + col) = make_float2(O[mb][dt][2], O[mb][dt][3]);
        }
    }
}

extern "C" void kernel_launch(void* const* d_in, const int* in_sizes, int n_in,
                              void* d_out, int out_size)
{
    const float* Q    = (const float*)d_in[0];
    const float* K    = (const float*)d_in[1];
    const float* V    = (const float*)d_in[2];
    const int*   mask = (const int*)d_in[3];

    float* Out  = (float*)d_out;
    float* Attn = Out + (size_t)BHn * Sn * Dn;

    cudaFuncSetAttribute(attn_hmma, cudaFuncAttributeMaxDynamicSharedMemorySize, SMEM_BYTES);

    dim3 grid(Sn / MQ, BHn);
    attn_hmma<<<grid, NT, SMEM_BYTES>>>(Q, K, V, mask, Out, Attn);
}

// round 8
// speedup vs baseline: 3.9068x; 1.0754x over previous
#include <cuda_runtime.h>
#include <cuda_fp16.h>
#include <cstdint>

// ---------------- problem shape ----------------
#define Bn 4
#define Hn 16
#define Sn 2048
#define Dn 64
#define BHn (Bn*Hn)
#define MQ 128            // queries per CTA
#define TN 128            // keys per smem tile
#define NTILES (Sn/TN)    // 16
#define NT 128            // threads, 4 warps; each warp owns 2 m-blocks (rows w*16 and w*16+64)

// ---------------- smem layout (bytes) ----------------
#define SM_QH   0
#define SM_KH   16384
#define SM_KL   32768
#define SM_VH   49152
#define SM_BIAS 65536     // 2048 floats: 0 or -1e30
#define SM_RS   73728
#define SM_INV  74240
#define SMEM_BYTES 74752  // x3 CTAs = 224256 <= 228KB/SM

__device__ __forceinline__ uint32_t swz(uint32_t o) { return o ^ ((o >> 3) & 0x70); }

__device__ __forceinline__ uint32_t s2u(const void* p) {
    uint32_t a;
    asm("{ .reg .u64 t; cvta.to.shared.u64 t, %1; cvt.u32.u64 %0, t; }" : "=r"(a) : "l"(p));
    return a;
}
__device__ __forceinline__ uint32_t ph2(float a, float b) {
    __half2 h = __floats2half2_rn(a, b);
    return *reinterpret_cast<uint32_t*>(&h);
}
__device__ __forceinline__ float hres(float x) {
    return x - __half2float(__float2half_rn(x));
}
__device__ __forceinline__ void ldsm4(uint32_t* r, uint32_t a) {
    asm volatile("ldmatrix.sync.aligned.m8n8.x4.shared.b16 {%0,%1,%2,%3}, [%4];"
        : "=r"(r[0]), "=r"(r[1]), "=r"(r[2]), "=r"(r[3]) : "r"(a));
}
__device__ __forceinline__ void ldsm4t(uint32_t* r, uint32_t a) {
    asm volatile("ldmatrix.sync.aligned.m8n8.x4.trans.shared.b16 {%0,%1,%2,%3}, [%4];"
        : "=r"(r[0]), "=r"(r[1]), "=r"(r[2]), "=r"(r[3]) : "r"(a));
}
__device__ __forceinline__ void mma16816(float* d, const uint32_t* a, const uint32_t* b) {
    asm volatile("mma.sync.aligned.m16n8k16.row.col.f32.f16.f16.f32 "
        "{%0,%1,%2,%3},{%4,%5,%6,%7},{%8,%9},{%0,%1,%2,%3};"
        : "+f"(d[0]), "+f"(d[1]), "+f"(d[2]), "+f"(d[3])
        : "r"(a[0]), "r"(a[1]), "r"(a[2]), "r"(a[3]), "r"(b[0]), "r"(b[1]));
}

// 128x64 fp32 tile -> fp16 hi+lo smem (swizzled 128B rows). NT=128 -> 8 iters.
__device__ __forceinline__ void load_tile_hl(const float* __restrict__ g, char* hi, char* lo, int tid) {
    #pragma unroll
    for (int it = 0; it < 8; ++it) {
        int chunk = tid + it * NT;
        int r = chunk >> 3, c8 = chunk & 7;
        const float4* p = (const float4*)(g + r * Dn + c8 * 8);
        float4 f0 = p[0], f1 = p[1];
        uint4 hv, lv;
        hv.x = ph2(f0.x, f0.y); hv.y = ph2(f0.z, f0.w);
        hv.z = ph2(f1.x, f1.y); hv.w = ph2(f1.z, f1.w);
        lv.x = ph2(hres(f0.x), hres(f0.y)); lv.y = ph2(hres(f0.z), hres(f0.w));
        lv.z = ph2(hres(f1.x), hres(f1.y)); lv.w = ph2(hres(f1.z), hres(f1.w));
        uint32_t off = swz((uint32_t)(r * 128 + c8 * 16));
        *(uint4*)(hi + off) = hv;
        *(uint4*)(lo + off) = lv;
    }
}
// hi-only variant (Q, V, and K in pass 1)
__device__ __forceinline__ void load_tile_h(const float* __restrict__ g, char* hi, int tid) {
    #pragma unroll
    for (int it = 0; it < 8; ++it) {
        int chunk = tid + it * NT;
        int r = chunk >> 3, c8 = chunk & 7;
        const float4* p = (const float4*)(g + r * Dn + c8 * 8);
        float4 f0 = p[0], f1 = p[1];
        uint4 hv;
        hv.x = ph2(f0.x, f0.y); hv.y = ph2(f0.z, f0.w);
        hv.z = ph2(f1.x, f1.y); hv.w = ph2(f1.z, f1.w);
        *(uint4*)(hi + swz((uint32_t)(r * 128 + c8 * 16))) = hv;
    }
}

__global__ __launch_bounds__(NT, 3)
void attn_hmma(const float* __restrict__ Q, const float* __restrict__ K,
               const float* __restrict__ V, const int* __restrict__ Mk,
               float* __restrict__ Out, float* __restrict__ Attn)
{
    extern __shared__ char smem[];
    const uint32_t su = s2u(smem);
    const int tid = threadIdx.x, w = tid >> 5, lane = tid & 31;
    const int bh = blockIdx.y, b = bh >> 4;
    const int q0 = blockIdx.x * MQ;
    const size_t qbase = ((size_t)bh * Sn + q0) * Dn;

    // mask -> float bias in smem (0 or -1e30)
    float* bias = (float*)(smem + SM_BIAS);
    #pragma unroll
    for (int i = 0; i < Sn / NT; ++i) {
        int idx = tid + i * NT;
        bias[idx] = Mk[(size_t)b * Sn + idx] ? 0.f : -1e30f;
    }

    // Q tile -> smem hi only (persists across both passes)
    load_tile_h(Q + qbase, smem + SM_QH, tid);
    __syncthreads();

    // per-mb "virtual warp" row: mb=0 -> w, mb=1 -> w+4
    const uint32_t qcs = ((lane >> 4) & 1) * 16;
    const int krb = (lane & 7) + ((lane >> 4) & 1) * 8;
    const uint32_t kcs = ((lane >> 3) & 1) * 16;
    const int cb0 = (lane & 3) * 2;
    int qr[2];
    qr[0] = w * 16 + (lane & 7) + ((lane >> 3) & 1) * 8;
    qr[1] = qr[0] + 64;

    // ============ Pass 1: 1-term (hi x hi), Q-hi frags hoisted, K shared over mb ============
    uint32_t qf[2][4][4];
    #pragma unroll
    for (int mb = 0; mb < 2; ++mb)
        #pragma unroll
        for (int ks = 0; ks < 4; ++ks)
            ldsm4(qf[mb][ks], su + SM_QH + swz((uint32_t)(qr[mb] * 128 + ks * 32) + qcs));

    float rs[2][2] = {{0.f, 0.f}, {0.f, 0.f}};
    for (int t = 0; t < NTILES; ++t) {
        if (t) __syncthreads();
        load_tile_h(K + ((size_t)bh * Sn + t * TN) * Dn, smem + SM_KH, tid);
        __syncthreads();
        #pragma unroll
        for (int c = 0; c < 2; ++c) {
            float c_[2][8][4];
            #pragma unroll
            for (int mb = 0; mb < 2; ++mb)
                #pragma unroll
                for (int nt = 0; nt < 8; ++nt)
                    #pragma unroll
                    for (int i = 0; i < 4; ++i) c_[mb][nt][i] = 0.f;
            #pragma unroll
            for (int ks = 0; ks < 4; ++ks) {
                #pragma unroll
                for (int pr = 0; pr < 4; ++pr) {
                    uint32_t bh_[4];
                    ldsm4(bh_, su + SM_KH + swz((uint32_t)((c * 64 + pr * 16 + krb) * 128 + ks * 32) + kcs));
                    #pragma unroll
                    for (int mb = 0; mb < 2; ++mb) {
                        mma16816(c_[mb][2 * pr],     qf[mb][ks], bh_);
                        mma16816(c_[mb][2 * pr + 1], qf[mb][ks], bh_ + 2);
                    }
                }
            }
            const float* bp = bias + t * TN + c * 64 + cb0;
            #pragma unroll
            for (int nt = 0; nt < 8; ++nt) {
                float2 bb = *(const float2*)(bp + nt * 8);
                #pragma unroll
                for (int mb = 0; mb < 2; ++mb) {
                    rs[mb][0] += __expf(fmaf(c_[mb][nt][0], 0.125f, bb.x)) + __expf(fmaf(c_[mb][nt][1], 0.125f, bb.y));
                    rs[mb][1] += __expf(fmaf(c_[mb][nt][2], 0.125f, bb.x)) + __expf(fmaf(c_[mb][nt][3], 0.125f, bb.y));
                }
            }
        }
    }
    #pragma unroll
    for (int mb = 0; mb < 2; ++mb)
        #pragma unroll
        for (int h = 0; h < 2; ++h) {
            rs[mb][h] += __shfl_xor_sync(~0u, rs[mb][h], 1);
            rs[mb][h] += __shfl_xor_sync(~0u, rs[mb][h], 2);
        }
    float* rsm = (float*)(smem + SM_RS);
    if ((lane & 3) == 0) {
        #pragma unroll
        for (int mb = 0; mb < 2; ++mb) {
            int r = (w + 4 * mb) * 16 + (lane >> 2);
            rsm[r]     = rs[mb][0];
            rsm[r + 8] = rs[mb][1];
        }
    }
    __syncthreads();
    float* invm = (float*)(smem + SM_INV);
    invm[tid] = 1.0f / rsm[tid];
    __syncthreads();
    float inv_[2][2];
    #pragma unroll
    for (int mb = 0; mb < 2; ++mb) {
        inv_[mb][0] = invm[(w + 4 * mb) * 16 + (lane >> 2)];
        inv_[mb][1] = invm[(w + 4 * mb) * 16 + 8 + (lane >> 2)];
    }

    // ============ Pass 2: 2-term QK (Qhi x (Khi+Klo)), attn write, 1-term PV ============
    float O[2][8][4];
    #pragma unroll
    for (int mb = 0; mb < 2; ++mb)
        #pragma unroll
        for (int j = 0; j < 8; ++j)
            #pragma unroll
            for (int i = 0; i < 4; ++i) O[mb][j][i] = 0.f;

    const int vrb = (lane & 7) + ((lane >> 3) & 1) * 8;
    const uint32_t vcs = ((lane >> 4) & 1) * 16;
    float* ar[2][2];
    #pragma unroll
    for (int mb = 0; mb < 2; ++mb) {
        ar[mb][0] = Attn + ((size_t)bh * Sn + q0 + (w + 4 * mb) * 16 + (lane >> 2)) * Sn;
        ar[mb][1] = ar[mb][0] + (size_t)8 * Sn;
    }

    for (int t = 0; t < NTILES; ++t) {
        __syncthreads();
        load_tile_hl(K + ((size_t)bh * Sn + t * TN) * Dn, smem + SM_KH, smem + SM_KL, tid);
        load_tile_h (V + ((size_t)bh * Sn + t * TN) * Dn, smem + SM_VH, tid);
        __syncthreads();
        #pragma unroll
        for (int c = 0; c < 2; ++c) {
            float c_[2][8][4];
            #pragma unroll
            for (int mb = 0; mb < 2; ++mb)
                #pragma unroll
                for (int nt = 0; nt < 8; ++nt)
                    #pragma unroll
                    for (int i = 0; i < 4; ++i) c_[mb][nt][i] = 0.f;
            #pragma unroll
            for (int ks = 0; ks < 4; ++ks) {
                uint32_t ah[2][4];
                #pragma unroll
                for (int mb = 0; mb < 2; ++mb)
                    ldsm4(ah[mb], su + SM_QH + swz((uint32_t)(qr[mb] * 128 + ks * 32) + qcs));
                #pragma unroll
                for (int pr = 0; pr < 4; ++pr) {
                    uint32_t koff = swz((uint32_t)((c * 64 + pr * 16 + krb) * 128 + ks * 32) + kcs);
                    uint32_t bh_[4], bl_[4];
                    ldsm4(bh_, su + SM_KH + koff);
                    ldsm4(bl_, su + SM_KL + koff);
                    #pragma unroll
                    for (int mb = 0; mb < 2; ++mb) {
                        mma16816(c_[mb][2 * pr],     ah[mb], bh_);
                        mma16816(c_[mb][2 * pr],     ah[mb], bl_);
                        mma16816(c_[mb][2 * pr + 1], ah[mb], bh_ + 2);
                        mma16816(c_[mb][2 * pr + 1], ah[mb], bl_ + 2);
                    }
                }
            }
            // epilogue: P = exp(s+bias)*inv, store attn, pack fragments (hi only)
            uint32_t PH[2][8][2];
            const float* bp = bias + t * TN + c * 64 + cb0;
            #pragma unroll
            for (int mb = 0; mb < 2; ++mb) {
                #pragma unroll
                for (int nt = 0; nt < 8; ++nt) {
                    int col = t * TN + c * 64 + nt * 8 + cb0;
                    float2 bb = *(const float2*)(bp + nt * 8);
                    float p0 = __expf(fmaf(c_[mb][nt][0], 0.125f, bb.x)) * inv_[mb][0];
                    float p1 = __expf(fmaf(c_[mb][nt][1], 0.125f, bb.y)) * inv_[mb][0];
                    float p2 = __expf(fmaf(c_[mb][nt][2], 0.125f, bb.x)) * inv_[mb][1];
                    float p3 = __expf(fmaf(c_[mb][nt][3], 0.125f, bb.y)) * inv_[mb][1];
                    *(float2*)(ar[mb][0] + col) = make_float2(p0, p1);
                    *(float2*)(ar[mb][1] + col) = make_float2(p2, p3);
                    PH[mb][nt][0] = ph2(p0, p1);
                    PH[mb][nt][1] = ph2(p2, p3);
                }
            }
            // PV: V fragments loaded once, consumed by both m-blocks (1-term)
            #pragma unroll
            for (int kp = 0; kp < 4; ++kp) {
                uint32_t pah[2][4];
                #pragma unroll
                for (int mb = 0; mb < 2; ++mb) {
                    pah[mb][0] = PH[mb][2*kp][0];   pah[mb][1] = PH[mb][2*kp][1];
                    pah[mb][2] = PH[mb][2*kp+1][0]; pah[mb][3] = PH[mb][2*kp+1][1];
                }
                int vrow = c * 64 + kp * 16 + vrb;
                #pragma unroll
                for (int dp = 0; dp < 4; ++dp) {
                    uint32_t vo = swz((uint32_t)(vrow * 128 + dp * 32) + vcs);
                    uint32_t vb[4];
                    ldsm4t(vb, su + SM_VH + vo);
                    #pragma unroll
                    for (int mb = 0; mb < 2; ++mb) {
                        mma16816(O[mb][2 * dp],     pah[mb], vb);
                        mma16816(O[mb][2 * dp + 1], pah[mb], vb + 2);
                    }
                }
            }
        }
    }

    // ============ O writeback ============
    #pragma unroll
    for (int mb = 0; mb < 2; ++mb) {
        float* orow0 = Out + ((size_t)bh * Sn + q0 + (w + 4 * mb) * 16 + (lane >> 2)) * Dn;
        float* orow1 = orow0 + 8 * Dn;
        #pragma unroll
        for (int dt = 0; dt < 8; ++dt) {
            int col = dt * 8 + cb0;
            *(float2*)(orow0 + col) = make_float2(O[mb][dt][0], O[mb][dt][1]);
            *(float2*)(orow1 + col) = make_float2(O[mb][dt][2], O[mb][dt][3]);
        }
    }
}

extern "C" void kernel_launch(void* const* d_in, const int* in_sizes, int n_in,
                              void* d_out, int out_size)
{
    const float* Q    = (const float*)d_in[0];
    const float* K    = (const float*)d_in[1];
    const float* V    = (const float*)d_in[2];
    const int*   mask = (const int*)d_in[3];

    float* Out  = (float*)d_out;
    float* Attn = Out + (size_t)BHn * Sn * Dn;

    cudaFuncSetAttribute(attn_hmma, cudaFuncAttributeMaxDynamicSharedMemorySize, SMEM_BYTES);

    dim3 grid(Sn / MQ, BHn);
    attn_hmma<<<grid, NT, SMEM_BYTES>>>(Q, K, V, mask, Out, Attn);
}

// round 9
// speedup vs baseline: 4.3734x; 1.1194x over previous
#include <cuda_runtime.h>
#include <cuda_fp16.h>
#include <cstdint>

// ---------------- problem shape ----------------
#define Bn 4
#define Hn 16
#define Sn 2048
#define Dn 64
#define BHn (Bn*Hn)
#define MQ 128            // queries per CTA
#define TN 128            // keys per smem tile
#define NTILES (Sn/TN)    // 16
#define NT 128            // threads, 4 warps; each warp owns 2 m-blocks (rows w*16 and w*16+64)

// ---------------- smem layout (bytes) ----------------
#define SM_QH   0
#define SM_KH   16384
#define SM_VH   32768
#define SM_BIAS 49152     // 2048 floats: 0 or -1e30
#define SM_RS   57344
#define SM_INV  57856
#define SMEM_BYTES 58368  // x3 CTAs = 175104 <= 228KB/SM

__device__ __forceinline__ uint32_t swz(uint32_t o) { return o ^ ((o >> 3) & 0x70); }

__device__ __forceinline__ uint32_t s2u(const void* p) {
    uint32_t a;
    asm("{ .reg .u64 t; cvta.to.shared.u64 t, %1; cvt.u32.u64 %0, t; }" : "=r"(a) : "l"(p));
    return a;
}
__device__ __forceinline__ uint32_t ph2(float a, float b) {
    __half2 h = __floats2half2_rn(a, b);
    return *reinterpret_cast<uint32_t*>(&h);
}
__device__ __forceinline__ void ldsm4(uint32_t* r, uint32_t a) {
    asm volatile("ldmatrix.sync.aligned.m8n8.x4.shared.b16 {%0,%1,%2,%3}, [%4];"
        : "=r"(r[0]), "=r"(r[1]), "=r"(r[2]), "=r"(r[3]) : "r"(a));
}
__device__ __forceinline__ void ldsm4t(uint32_t* r, uint32_t a) {
    asm volatile("ldmatrix.sync.aligned.m8n8.x4.trans.shared.b16 {%0,%1,%2,%3}, [%4];"
        : "=r"(r[0]), "=r"(r[1]), "=r"(r[2]), "=r"(r[3]) : "r"(a));
}
__device__ __forceinline__ void mma16816(float* d, const uint32_t* a, const uint32_t* b) {
    asm volatile("mma.sync.aligned.m16n8k16.row.col.f32.f16.f16.f32 "
        "{%0,%1,%2,%3},{%4,%5,%6,%7},{%8,%9},{%0,%1,%2,%3};"
        : "+f"(d[0]), "+f"(d[1]), "+f"(d[2]), "+f"(d[3])
        : "r"(a[0]), "r"(a[1]), "r"(a[2]), "r"(a[3]), "r"(b[0]), "r"(b[1]));
}

// 128x64 fp32 tile -> fp16 (hi) smem, swizzled 128B rows. NT=128 -> 8 iters.
__device__ __forceinline__ void load_tile_h(const float* __restrict__ g, char* hi, int tid) {
    #pragma unroll
    for (int it = 0; it < 8; ++it) {
        int chunk = tid + it * NT;
        int r = chunk >> 3, c8 = chunk & 7;
        const float4* p = (const float4*)(g + r * Dn + c8 * 8);
        float4 f0 = p[0], f1 = p[1];
        uint4 hv;
        hv.x = ph2(f0.x, f0.y); hv.y = ph2(f0.z, f0.w);
        hv.z = ph2(f1.x, f1.y); hv.w = ph2(f1.z, f1.w);
        *(uint4*)(hi + swz((uint32_t)(r * 128 + c8 * 16))) = hv;
    }
}

__global__ __launch_bounds__(NT, 3)
void attn_hmma(const float* __restrict__ Q, const float* __restrict__ K,
               const float* __restrict__ V, const int* __restrict__ Mk,
               float* __restrict__ Out, float* __restrict__ Attn)
{
    extern __shared__ char smem[];
    const uint32_t su = s2u(smem);
    const int tid = threadIdx.x, w = tid >> 5, lane = tid & 31;
    const int bh = blockIdx.y, b = bh >> 4;
    const int q0 = blockIdx.x * MQ;
    const size_t qbase = ((size_t)bh * Sn + q0) * Dn;

    // mask -> float bias in smem (0 or -1e30)
    float* bias = (float*)(smem + SM_BIAS);
    #pragma unroll
    for (int i = 0; i < Sn / NT; ++i) {
        int idx = tid + i * NT;
        bias[idx] = Mk[(size_t)b * Sn + idx] ? 0.f : -1e30f;
    }

    // Q tile -> smem (persists across both passes)
    load_tile_h(Q + qbase, smem + SM_QH, tid);
    __syncthreads();

    // per-mb "virtual warp" row: mb=0 -> w, mb=1 -> w+4
    const uint32_t qcs = ((lane >> 4) & 1) * 16;
    const int krb = (lane & 7) + ((lane >> 4) & 1) * 8;
    const uint32_t kcs = ((lane >> 3) & 1) * 16;
    const int cb0 = (lane & 3) * 2;
    int qr[2];
    qr[0] = w * 16 + (lane & 7) + ((lane >> 3) & 1) * 8;
    qr[1] = qr[0] + 64;

    // ============ Pass 1: row sums; Q frags hoisted, K shared over mb ============
    {
        uint32_t qf[2][4][4];
        #pragma unroll
        for (int mb = 0; mb < 2; ++mb)
            #pragma unroll
            for (int ks = 0; ks < 4; ++ks)
                ldsm4(qf[mb][ks], su + SM_QH + swz((uint32_t)(qr[mb] * 128 + ks * 32) + qcs));

        float rs[2][2] = {{0.f, 0.f}, {0.f, 0.f}};
        for (int t = 0; t < NTILES; ++t) {
            if (t) __syncthreads();
            load_tile_h(K + ((size_t)bh * Sn + t * TN) * Dn, smem + SM_KH, tid);
            __syncthreads();
            #pragma unroll
            for (int c = 0; c < 2; ++c) {
                float c_[2][8][4];
                #pragma unroll
                for (int mb = 0; mb < 2; ++mb)
                    #pragma unroll
                    for (int nt = 0; nt < 8; ++nt)
                        #pragma unroll
                        for (int i = 0; i < 4; ++i) c_[mb][nt][i] = 0.f;
                #pragma unroll
                for (int ks = 0; ks < 4; ++ks) {
                    #pragma unroll
                    for (int pr = 0; pr < 4; ++pr) {
                        uint32_t bh_[4];
                        ldsm4(bh_, su + SM_KH + swz((uint32_t)((c * 64 + pr * 16 + krb) * 128 + ks * 32) + kcs));
                        #pragma unroll
                        for (int mb = 0; mb < 2; ++mb) {
                            mma16816(c_[mb][2 * pr],     qf[mb][ks], bh_);
                            mma16816(c_[mb][2 * pr + 1], qf[mb][ks], bh_ + 2);
                        }
                    }
                }
                const float* bp = bias + t * TN + c * 64 + cb0;
                #pragma unroll
                for (int nt = 0; nt < 8; ++nt) {
                    float2 bb = *(const float2*)(bp + nt * 8);
                    #pragma unroll
                    for (int mb = 0; mb < 2; ++mb) {
                        rs[mb][0] += __expf(fmaf(c_[mb][nt][0], 0.125f, bb.x)) + __expf(fmaf(c_[mb][nt][1], 0.125f, bb.y));
                        rs[mb][1] += __expf(fmaf(c_[mb][nt][2], 0.125f, bb.x)) + __expf(fmaf(c_[mb][nt][3], 0.125f, bb.y));
                    }
                }
            }
        }
        #pragma unroll
        for (int mb = 0; mb < 2; ++mb)
            #pragma unroll
            for (int h = 0; h < 2; ++h) {
                rs[mb][h] += __shfl_xor_sync(~0u, rs[mb][h], 1);
                rs[mb][h] += __shfl_xor_sync(~0u, rs[mb][h], 2);
            }
        float* rsm = (float*)(smem + SM_RS);
        if ((lane & 3) == 0) {
            #pragma unroll
            for (int mb = 0; mb < 2; ++mb) {
                int r = (w + 4 * mb) * 16 + (lane >> 2);
                rsm[r]     = rs[mb][0];
                rsm[r + 8] = rs[mb][1];
            }
        }
    }
    __syncthreads();
    {
        float* rsm = (float*)(smem + SM_RS);
        float* invm = (float*)(smem + SM_INV);
        invm[tid] = 1.0f / rsm[tid];
    }
    __syncthreads();
    float inv_[2][2];
    {
        const float* invm = (const float*)(smem + SM_INV);
        #pragma unroll
        for (int mb = 0; mb < 2; ++mb) {
            inv_[mb][0] = invm[(w + 4 * mb) * 16 + (lane >> 2)];
            inv_[mb][1] = invm[(w + 4 * mb) * 16 + 8 + (lane >> 2)];
        }
    }

    // ============ Pass 2: QK, attn write, PV; K/V frags shared over mb ============
    float O[2][8][4];
    #pragma unroll
    for (int mb = 0; mb < 2; ++mb)
        #pragma unroll
        for (int j = 0; j < 8; ++j)
            #pragma unroll
            for (int i = 0; i < 4; ++i) O[mb][j][i] = 0.f;

    const int vrb = (lane & 7) + ((lane >> 3) & 1) * 8;
    const uint32_t vcs = ((lane >> 4) & 1) * 16;
    float* ar[2][2];
    #pragma unroll
    for (int mb = 0; mb < 2; ++mb) {
        ar[mb][0] = Attn + ((size_t)bh * Sn + q0 + (w + 4 * mb) * 16 + (lane >> 2)) * Sn;
        ar[mb][1] = ar[mb][0] + (size_t)8 * Sn;
    }

    for (int t = 0; t < NTILES; ++t) {
        __syncthreads();
        load_tile_h(K + ((size_t)bh * Sn + t * TN) * Dn, smem + SM_KH, tid);
        load_tile_h(V + ((size_t)bh * Sn + t * TN) * Dn, smem + SM_VH, tid);
        __syncthreads();
        #pragma unroll
        for (int c = 0; c < 2; ++c) {
            float c_[2][8][4];
            #pragma unroll
            for (int mb = 0; mb < 2; ++mb)
                #pragma unroll
                for (int nt = 0; nt < 8; ++nt)
                    #pragma unroll
                    for (int i = 0; i < 4; ++i) c_[mb][nt][i] = 0.f;
            #pragma unroll
            for (int ks = 0; ks < 4; ++ks) {
                uint32_t ah[2][4];
                #pragma unroll
                for (int mb = 0; mb < 2; ++mb)
                    ldsm4(ah[mb], su + SM_QH + swz((uint32_t)(qr[mb] * 128 + ks * 32) + qcs));
                #pragma unroll
                for (int pr = 0; pr < 4; ++pr) {
                    uint32_t bh_[4];
                    ldsm4(bh_, su + SM_KH + swz((uint32_t)((c * 64 + pr * 16 + krb) * 128 + ks * 32) + kcs));
                    #pragma unroll
                    for (int mb = 0; mb < 2; ++mb) {
                        mma16816(c_[mb][2 * pr],     ah[mb], bh_);
                        mma16816(c_[mb][2 * pr + 1], ah[mb], bh_ + 2);
                    }
                }
            }
            // epilogue: P = exp(s+bias)*inv, store attn, pack fragments
            uint32_t PH[2][8][2];
            const float* bp = bias + t * TN + c * 64 + cb0;
            #pragma unroll
            for (int mb = 0; mb < 2; ++mb) {
                #pragma unroll
                for (int nt = 0; nt < 8; ++nt) {
                    int col = t * TN + c * 64 + nt * 8 + cb0;
                    float2 bb = *(const float2*)(bp + nt * 8);
                    float p0 = __expf(fmaf(c_[mb][nt][0], 0.125f, bb.x)) * inv_[mb][0];
                    float p1 = __expf(fmaf(c_[mb][nt][1], 0.125f, bb.y)) * inv_[mb][0];
                    float p2 = __expf(fmaf(c_[mb][nt][2], 0.125f, bb.x)) * inv_[mb][1];
                    float p3 = __expf(fmaf(c_[mb][nt][3], 0.125f, bb.y)) * inv_[mb][1];
                    *(float2*)(ar[mb][0] + col) = make_float2(p0, p1);
                    *(float2*)(ar[mb][1] + col) = make_float2(p2, p3);
                    PH[mb][nt][0] = ph2(p0, p1);
                    PH[mb][nt][1] = ph2(p2, p3);
                }
            }
            // PV: V fragments loaded once, consumed by both m-blocks
            #pragma unroll
            for (int kp = 0; kp < 4; ++kp) {
                uint32_t pah[2][4];
                #pragma unroll
                for (int mb = 0; mb < 2; ++mb) {
                    pah[mb][0] = PH[mb][2*kp][0];   pah[mb][1] = PH[mb][2*kp][1];
                    pah[mb][2] = PH[mb][2*kp+1][0]; pah[mb][3] = PH[mb][2*kp+1][1];
                }
                int vrow = c * 64 + kp * 16 + vrb;
                #pragma unroll
                for (int dp = 0; dp < 4; ++dp) {
                    uint32_t vo = swz((uint32_t)(vrow * 128 + dp * 32) + vcs);
                    uint32_t vb[4];
                    ldsm4t(vb, su + SM_VH + vo);
                    #pragma unroll
                    for (int mb = 0; mb < 2; ++mb) {
                        mma16816(O[mb][2 * dp],     pah[mb], vb);
                        mma16816(O[mb][2 * dp + 1], pah[mb], vb + 2);
                    }
                }
            }
        }
    }

    // ============ O writeback ============
    #pragma unroll
    for (int mb = 0; mb < 2; ++mb) {
        float* orow0 = Out + ((size_t)bh * Sn + q0 + (w + 4 * mb) * 16 + (lane >> 2)) * Dn;
        float* orow1 = orow0 + 8 * Dn;
        #pragma unroll
        for (int dt = 0; dt < 8; ++dt) {
            int col = dt * 8 + cb0;
            *(float2*)(orow0 + col) = make_float2(O[mb][dt][0], O[mb][dt][1]);
            *(float2*)(orow1 + col) = make_float2(O[mb][dt][2], O[mb][dt][3]);
        }
    }
}

extern "C" void kernel_launch(void* const* d_in, const int* in_sizes, int n_in,
                              void* d_out, int out_size)
{
    const float* Q    = (const float*)d_in[0];
    const float* K    = (const float*)d_in[1];
    const float* V    = (const float*)d_in[2];
    const int*   mask = (const int*)d_in[3];

    float* Out  = (float*)d_out;
    float* Attn = Out + (size_t)BHn * Sn * Dn;

    cudaFuncSetAttribute(attn_hmma, cudaFuncAttributeMaxDynamicSharedMemorySize, SMEM_BYTES);

    dim3 grid(Sn / MQ, BHn);
    attn_hmma<<<grid, NT, SMEM_BYTES>>>(Q, K, V, mask, Out, Attn);
}